// round 2
// baseline (speedup 1.0000x reference)
#include <cuda_runtime.h>
#include <math.h>

#define N_TOK 2048
#define DIM   1024
#define HEADS 16
#define DHEAD 64
#define INNER 1024
#define FFDIM 4096
#define LAYERS 4
#define QKVW  (3*INNER)

// ---------------- scratch (no allocation allowed) ----------------
__device__ float g_h  [N_TOK * DIM];
__device__ float g_y  [N_TOK * DIM];
__device__ float g_qkv[N_TOK * QKVW];
__device__ float g_o  [N_TOK * INNER];
__device__ float g_z  [N_TOK * FFDIM];

// ---------------- layernorm: one block per row ----------------
__global__ void ln_kernel(const float* __restrict__ in,
                          const float* __restrict__ g,
                          const float* __restrict__ b,
                          float* __restrict__ out) {
    int row = blockIdx.x;
    int tid = threadIdx.x;  // 256 threads, 4 floats each
    float4 v = ((const float4*)(in + (size_t)row * DIM))[tid];
    float s = v.x + v.y + v.z + v.w;
    float q = v.x*v.x + v.y*v.y + v.z*v.z + v.w*v.w;
    #pragma unroll
    for (int off = 16; off; off >>= 1) {
        s += __shfl_xor_sync(0xFFFFFFFFu, s, off);
        q += __shfl_xor_sync(0xFFFFFFFFu, q, off);
    }
    __shared__ float ss[8], qq[8];
    __shared__ float mean_s, rstd_s;
    int w = tid >> 5;
    if ((tid & 31) == 0) { ss[w] = s; qq[w] = q; }
    __syncthreads();
    if (tid == 0) {
        float S = 0.f, Q = 0.f;
        #pragma unroll
        for (int i = 0; i < 8; i++) { S += ss[i]; Q += qq[i]; }
        float mean = S * (1.0f / DIM);
        float var  = Q * (1.0f / DIM) - mean * mean;
        mean_s = mean;
        rstd_s = rsqrtf(var + 1e-5f);
    }
    __syncthreads();
    float mean = mean_s, rstd = rstd_s;
    float4 gg = ((const float4*)g)[tid];
    float4 bb = ((const float4*)b)[tid];
    float4 o;
    o.x = (v.x - mean) * rstd * gg.x + bb.x;
    o.y = (v.y - mean) * rstd * gg.y + bb.y;
    o.z = (v.z - mean) * rstd * gg.z + bb.z;
    o.w = (v.w - mean) * rstd * gg.w + bb.w;
    ((float4*)(out + (size_t)row * DIM))[tid] = o;
}

// ---------------- SGEMM: C[M,N] = A[M,K] @ B[K,N] (+bias)(gelu)(+res) ----
// 128x128 tile, BK=8, 256 threads, 8x8 microtile.
#define FLAG_BIAS 1
#define FLAG_GELU 2
#define FLAG_RES  4

__device__ __forceinline__ float gelu_exact(float x) {
    return 0.5f * x * (1.0f + erff(x * 0.70710678118654752f));
}

__global__ __launch_bounds__(256)
void sgemm_kernel(const float* __restrict__ A, const float* __restrict__ B,
                  const float* __restrict__ bias, const float* __restrict__ res,
                  float* __restrict__ C, int M, int N, int K, int flags) {
    __shared__ float As[8][128];
    __shared__ float Bs[8][128];
    int tid = threadIdx.x;
    int bx = blockIdx.x, by = blockIdx.y;

    int aRow = tid >> 1;            // 0..127
    int aCol = (tid & 1) << 2;      // 0 or 4
    int bRow = tid >> 5;            // 0..7
    int bCol = (tid & 31) << 2;     // 0..124

    const float* Ap = A + (size_t)(by * 128 + aRow) * K + aCol;
    const float* Bp = B + (size_t)bRow * N + bx * 128 + bCol;

    int tr = (tid >> 4) << 3;       // 0..120
    int tc = (tid & 15) << 3;       // 0..120

    float acc[8][8];
    #pragma unroll
    for (int i = 0; i < 8; i++)
        #pragma unroll
        for (int j = 0; j < 8; j++) acc[i][j] = 0.f;

    for (int k0 = 0; k0 < K; k0 += 8) {
        float4 a  = *(const float4*)Ap;
        float4 bq = *(const float4*)Bp;
        As[aCol + 0][aRow] = a.x;
        As[aCol + 1][aRow] = a.y;
        As[aCol + 2][aRow] = a.z;
        As[aCol + 3][aRow] = a.w;
        *(float4*)&Bs[bRow][bCol] = bq;
        __syncthreads();
        #pragma unroll
        for (int kk = 0; kk < 8; kk++) {
            float ar[8], br[8];
            *(float4*)(ar)     = *(const float4*)&As[kk][tr];
            *(float4*)(ar + 4) = *(const float4*)&As[kk][tr + 4];
            *(float4*)(br)     = *(const float4*)&Bs[kk][tc];
            *(float4*)(br + 4) = *(const float4*)&Bs[kk][tc + 4];
            #pragma unroll
            for (int i = 0; i < 8; i++)
                #pragma unroll
                for (int j = 0; j < 8; j++)
                    acc[i][j] += ar[i] * br[j];
        }
        __syncthreads();
        Ap += 8;
        Bp += (size_t)8 * N;
    }

    int row0 = by * 128 + tr;
    int col0 = bx * 128 + tc;
    #pragma unroll
    for (int i = 0; i < 8; i++) {
        #pragma unroll
        for (int j = 0; j < 8; j += 4) {
            float4 c;
            c.x = acc[i][j + 0];
            c.y = acc[i][j + 1];
            c.z = acc[i][j + 2];
            c.w = acc[i][j + 3];
            if (flags & FLAG_BIAS) {
                const float4 bb = *(const float4*)&bias[col0 + j];
                c.x += bb.x; c.y += bb.y; c.z += bb.z; c.w += bb.w;
            }
            if (flags & FLAG_GELU) {
                c.x = gelu_exact(c.x); c.y = gelu_exact(c.y);
                c.z = gelu_exact(c.z); c.w = gelu_exact(c.w);
            }
            if (flags & FLAG_RES) {
                const float4 r = *(const float4*)&res[(size_t)(row0 + i) * N + col0 + j];
                c.x += r.x; c.y += r.y; c.z += r.z; c.w += r.w;
            }
            *(float4*)&C[(size_t)(row0 + i) * N + col0 + j] = c;
        }
    }
}

// ---------------- attention: flash-style, 1 thread = 1 query row ------
// grid: (q_blocks=16, heads=16), block 128 threads. K/V tiles 32x64 in smem.
__global__ __launch_bounds__(128)
void attn_kernel(const float* __restrict__ qkv, float* __restrict__ o_out) {
    const int h   = blockIdx.y;
    const int qb  = blockIdx.x;
    const int tid = threadIdx.x;
    const int row = qb * 128 + tid;
    const float slope = exp2f(-0.5f * (float)(h + 1));

    __shared__ float Ks[32][DHEAD];
    __shared__ float Vs[32][DHEAD];

    float q[DHEAD];
    {
        const float* qp = qkv + (size_t)row * QKVW + h * DHEAD;
        #pragma unroll
        for (int i = 0; i < 16; i++) {
            float4 t = ((const float4*)qp)[i];
            q[4*i+0] = t.x * 0.125f;
            q[4*i+1] = t.y * 0.125f;
            q[4*i+2] = t.z * 0.125f;
            q[4*i+3] = t.w * 0.125f;
        }
    }

    float o[DHEAD];
    #pragma unroll
    for (int d = 0; d < DHEAD; d++) o[d] = 0.f;
    float m = -INFINITY, l = 0.f;

    const int ntiles = qb * 4 + 4;  // keys 0 .. qb*128+127, 32 per tile
    for (int kb = 0; kb < ntiles; kb++) {
        __syncthreads();
        #pragma unroll
        for (int it = 0; it < 16; it++) {
            int idx = tid + it * 128;
            int t = idx >> 6, d = idx & 63;
            size_t base = (size_t)(kb * 32 + t) * QKVW + h * DHEAD + d;
            Ks[t][d] = qkv[base + INNER];       // K block
            Vs[t][d] = qkv[base + 2 * INNER];   // V block
        }
        __syncthreads();

        if (kb * 32 <= row) {
            float s[32];
            float tmax = -INFINITY;
            #pragma unroll
            for (int t = 0; t < 32; t++) {
                int j = kb * 32 + t;
                float acc = 0.f;
                #pragma unroll
                for (int d = 0; d < DHEAD; d++) acc += q[d] * Ks[t][d];
                acc += slope * (float)j;
                s[t] = (j <= row) ? acc : -INFINITY;
                tmax = fmaxf(tmax, s[t]);
            }
            float mnew = fmaxf(m, tmax);      // tmax finite here
            float corr = __expf(m - mnew);    // m=-inf first tile -> 0
            l *= corr;
            #pragma unroll
            for (int d = 0; d < DHEAD; d++) o[d] *= corr;
            #pragma unroll
            for (int t = 0; t < 32; t++) {
                float p = __expf(s[t] - mnew);  // masked -> exp(-inf)=0
                l += p;
                #pragma unroll
                for (int d = 0; d < DHEAD; d++) o[d] += p * Vs[t][d];
            }
            m = mnew;
        }
    }

    float inv = 1.0f / l;
    float* op = o_out + (size_t)row * INNER + h * DHEAD;
    #pragma unroll
    for (int i = 0; i < 16; i++) {
        float4 t;
        t.x = o[4*i+0] * inv;
        t.y = o[4*i+1] * inv;
        t.z = o[4*i+2] * inv;
        t.w = o[4*i+3] * inv;
        ((float4*)op)[i] = t;
    }
}

// ---------------- orchestration ----------------
extern "C" void kernel_launch(void* const* d_in, const int* in_sizes, int n_in,
                              void* d_out, int out_size) {
    const float* x      = (const float*)d_in[0];
    const float* qkv_w  = (const float*)d_in[1];
    const float* out_w  = (const float*)d_in[2];
    const float* attn_g = (const float*)d_in[3];
    const float* attn_b = (const float*)d_in[4];
    const float* ff_g   = (const float*)d_in[5];
    const float* ff_b   = (const float*)d_in[6];
    const float* ff_w1  = (const float*)d_in[7];
    const float* ff_b1  = (const float*)d_in[8];
    const float* ff_w2  = (const float*)d_in[9];
    const float* ff_b2  = (const float*)d_in[10];
    const float* fin_g  = (const float*)d_in[11];
    const float* fin_b  = (const float*)d_in[12];
    float* out = (float*)d_out;

    float *h, *y, *qkv, *o, *z;
    cudaGetSymbolAddress((void**)&h,   g_h);
    cudaGetSymbolAddress((void**)&y,   g_y);
    cudaGetSymbolAddress((void**)&qkv, g_qkv);
    cudaGetSymbolAddress((void**)&o,   g_o);
    cudaGetSymbolAddress((void**)&z,   g_z);

    cudaMemcpyAsync(h, x, (size_t)N_TOK * DIM * sizeof(float),
                    cudaMemcpyDeviceToDevice);

    for (int l = 0; l < LAYERS; l++) {
        // ---- attention block ----
        ln_kernel<<<N_TOK, 256>>>(h, attn_g + l * DIM, attn_b + l * DIM, y);
        sgemm_kernel<<<dim3(QKVW / 128, N_TOK / 128), 256>>>(
            y, qkv_w + (size_t)l * DIM * QKVW, nullptr, nullptr, qkv,
            N_TOK, QKVW, DIM, 0);
        attn_kernel<<<dim3(N_TOK / 128, HEADS), 128>>>(qkv, o);
        sgemm_kernel<<<dim3(DIM / 128, N_TOK / 128), 256>>>(
            o, out_w + (size_t)l * INNER * DIM, nullptr, h, h,
            N_TOK, DIM, INNER, FLAG_RES);
        // ---- feed-forward block ----
        ln_kernel<<<N_TOK, 256>>>(h, ff_g + l * DIM, ff_b + l * DIM, y);
        sgemm_kernel<<<dim3(FFDIM / 128, N_TOK / 128), 256>>>(
            y, ff_w1 + (size_t)l * DIM * FFDIM, ff_b1 + (size_t)l * FFDIM,
            nullptr, z, N_TOK, FFDIM, DIM, FLAG_BIAS | FLAG_GELU);
        sgemm_kernel<<<dim3(DIM / 128, N_TOK / 128), 256>>>(
            z, ff_w2 + (size_t)l * FFDIM * DIM, ff_b2 + (size_t)l * DIM,
            h, h, N_TOK, DIM, FFDIM, FLAG_BIAS | FLAG_RES);
    }
    ln_kernel<<<N_TOK, 256>>>(h, fin_g, fin_b, out);
}

// round 3
// speedup vs baseline: 1.9974x; 1.9974x over previous
#include <cuda_runtime.h>
#include <math.h>
#include <stdint.h>

#define N_TOK 2048
#define DIM   1024
#define HEADS 16
#define DHEAD 64
#define INNER 1024
#define FFDIM 4096
#define LAYERS 4
#define QKVW  (3*INNER)

// ---------------- scratch (no allocation allowed) ----------------
__device__ float g_h  [N_TOK * DIM];
__device__ float g_y  [N_TOK * DIM];
__device__ float g_qkv[N_TOK * QKVW];
__device__ float g_o  [N_TOK * INNER];
__device__ float g_z  [N_TOK * FFDIM];

// ---------------- layernorm: one block per row ----------------
__global__ void ln_kernel(const float* __restrict__ in,
                          const float* __restrict__ g,
                          const float* __restrict__ b,
                          float* __restrict__ out) {
    int row = blockIdx.x;
    int tid = threadIdx.x;  // 256 threads, 4 floats each
    float4 v = ((const float4*)(in + (size_t)row * DIM))[tid];
    float s = v.x + v.y + v.z + v.w;
    float q = v.x*v.x + v.y*v.y + v.z*v.z + v.w*v.w;
    #pragma unroll
    for (int off = 16; off; off >>= 1) {
        s += __shfl_xor_sync(0xFFFFFFFFu, s, off);
        q += __shfl_xor_sync(0xFFFFFFFFu, q, off);
    }
    __shared__ float ss[8], qq[8];
    __shared__ float mean_s, rstd_s;
    int w = tid >> 5;
    if ((tid & 31) == 0) { ss[w] = s; qq[w] = q; }
    __syncthreads();
    if (tid == 0) {
        float S = 0.f, Q = 0.f;
        #pragma unroll
        for (int i = 0; i < 8; i++) { S += ss[i]; Q += qq[i]; }
        float mean = S * (1.0f / DIM);
        float var  = Q * (1.0f / DIM) - mean * mean;
        mean_s = mean;
        rstd_s = rsqrtf(var + 1e-5f);
    }
    __syncthreads();
    float mean = mean_s, rstd = rstd_s;
    float4 gg = ((const float4*)g)[tid];
    float4 bb = ((const float4*)b)[tid];
    float4 o;
    o.x = (v.x - mean) * rstd * gg.x + bb.x;
    o.y = (v.y - mean) * rstd * gg.y + bb.y;
    o.z = (v.z - mean) * rstd * gg.z + bb.z;
    o.w = (v.w - mean) * rstd * gg.w + bb.w;
    ((float4*)(out + (size_t)row * DIM))[tid] = o;
}

// ---------------- TF32 tensor-core GEMM ----------------
// C[M,N] = A[M,K] @ B[K,N] (+bias)(gelu)(+res)
// BM=128, BN template (128 or 64), BK=16, 256 threads (8 warps).
// Warp grid 2x4; warp tile 64 x (BN/4). mma.sync m16n8k8 tf32.
#define FLAG_BIAS 1
#define FLAG_GELU 2
#define FLAG_RES  4

__device__ __forceinline__ float gelu_exact(float x) {
    return 0.5f * x * (1.0f + erff(x * 0.70710678118654752f));
}

__device__ __forceinline__ uint32_t f2tf32(float x) {
    uint32_t u;
    asm("cvt.rna.tf32.f32 %0, %1;" : "=r"(u) : "f"(x));
    return u;
}

__device__ __forceinline__ void mma_tf32(float* c, const uint32_t* a, const uint32_t* b) {
    asm volatile(
        "mma.sync.aligned.m16n8k8.row.col.f32.tf32.tf32.f32 "
        "{%0,%1,%2,%3}, {%4,%5,%6,%7}, {%8,%9}, {%0,%1,%2,%3};"
        : "+f"(c[0]), "+f"(c[1]), "+f"(c[2]), "+f"(c[3])
        : "r"(a[0]), "r"(a[1]), "r"(a[2]), "r"(a[3]),
          "r"(b[0]), "r"(b[1]));
}

template<int BN>
__global__ __launch_bounds__(256)
void mma_gemm(const float* __restrict__ A, const float* __restrict__ B,
              const float* __restrict__ bias, const float* __restrict__ res,
              float* __restrict__ C, int M, int N, int K, int flags) {
    constexpr int BM = 128, BK = 16;
    constexpr int NF = BN / 32;          // n-frags per warp (4 or 2)
    constexpr int AST = BK + 4;          // 20 floats, conflict-free frag loads
    constexpr int BST = BN + 8;          // 136/72 -> stride%32==8, conflict-free
    constexpr int BF4 = BN / 4;          // float4 per B row
    constexpr int BIT = (BK * BF4) / 256;// B load iterations (2 or 1)

    __shared__ float As[2][BM * AST];
    __shared__ float Bs[2][BK * BST];

    const int tid  = threadIdx.x;
    const int lane = tid & 31;
    const int wid  = tid >> 5;
    const int gid  = lane >> 2;          // 0..7
    const int tig  = lane & 3;           // 0..3
    const int warp_m = wid >> 2;         // 0..1 (64 rows each)
    const int warp_n = wid & 3;          // 0..3 (BN/4 cols each)
    const int row0 = blockIdx.y * BM;
    const int col0 = blockIdx.x * BN;

    // A load mapping: rows ar, ar+64; 4 cols per float4
    const int ar = tid >> 2;
    const int ac = (tid & 3) << 2;
    // B load mapping
    int br[BIT], bc[BIT];
    #pragma unroll
    for (int it = 0; it < BIT; it++) {
        int idx = tid + it * 256;
        br[it] = idx / BF4;
        bc[it] = (idx % BF4) << 2;
    }

    float acc[4][NF][4];
    #pragma unroll
    for (int i = 0; i < 4; i++)
        #pragma unroll
        for (int j = 0; j < NF; j++)
            #pragma unroll
            for (int r = 0; r < 4; r++) acc[i][j][r] = 0.f;

    float4 a_stg[2];
    float4 b_stg[BIT];

    const int KT = K / BK;

    // prologue: stage + store tile 0
    a_stg[0] = *(const float4*)(A + (size_t)(row0 + ar) * K + ac);
    a_stg[1] = *(const float4*)(A + (size_t)(row0 + ar + 64) * K + ac);
    #pragma unroll
    for (int it = 0; it < BIT; it++)
        b_stg[it] = *(const float4*)(B + (size_t)br[it] * N + col0 + bc[it]);
    {
        float* as = As[0];
        as[ar * AST + ac + 0] = __uint_as_float(f2tf32(a_stg[0].x));
        as[ar * AST + ac + 1] = __uint_as_float(f2tf32(a_stg[0].y));
        as[ar * AST + ac + 2] = __uint_as_float(f2tf32(a_stg[0].z));
        as[ar * AST + ac + 3] = __uint_as_float(f2tf32(a_stg[0].w));
        as[(ar + 64) * AST + ac + 0] = __uint_as_float(f2tf32(a_stg[1].x));
        as[(ar + 64) * AST + ac + 1] = __uint_as_float(f2tf32(a_stg[1].y));
        as[(ar + 64) * AST + ac + 2] = __uint_as_float(f2tf32(a_stg[1].z));
        as[(ar + 64) * AST + ac + 3] = __uint_as_float(f2tf32(a_stg[1].w));
        float* bs = Bs[0];
        #pragma unroll
        for (int it = 0; it < BIT; it++) {
            bs[br[it] * BST + bc[it] + 0] = __uint_as_float(f2tf32(b_stg[it].x));
            bs[br[it] * BST + bc[it] + 1] = __uint_as_float(f2tf32(b_stg[it].y));
            bs[br[it] * BST + bc[it] + 2] = __uint_as_float(f2tf32(b_stg[it].z));
            bs[br[it] * BST + bc[it] + 3] = __uint_as_float(f2tf32(b_stg[it].w));
        }
    }
    __syncthreads();

    for (int kt = 0; kt < KT; kt++) {
        const int buf = kt & 1;
        // stage next tile from gmem (latency overlapped with compute)
        if (kt + 1 < KT) {
            const int k0 = (kt + 1) * BK;
            a_stg[0] = *(const float4*)(A + (size_t)(row0 + ar) * K + k0 + ac);
            a_stg[1] = *(const float4*)(A + (size_t)(row0 + ar + 64) * K + k0 + ac);
            #pragma unroll
            for (int it = 0; it < BIT; it++)
                b_stg[it] = *(const float4*)(B + (size_t)(k0 + br[it]) * N + col0 + bc[it]);
        }

        // compute on current buffer
        const float* as = As[buf];
        const float* bs = Bs[buf];
        #pragma unroll
        for (int ks = 0; ks < 2; ks++) {
            const int k8 = ks * 8;
            uint32_t af[4][4];
            #pragma unroll
            for (int fm = 0; fm < 4; fm++) {
                const int m = warp_m * 64 + fm * 16;
                af[fm][0] = __float_as_uint(as[(m + gid)     * AST + k8 + tig]);
                af[fm][1] = __float_as_uint(as[(m + gid + 8) * AST + k8 + tig]);
                af[fm][2] = __float_as_uint(as[(m + gid)     * AST + k8 + tig + 4]);
                af[fm][3] = __float_as_uint(as[(m + gid + 8) * AST + k8 + tig + 4]);
            }
            uint32_t bf[NF][2];
            #pragma unroll
            for (int fn = 0; fn < NF; fn++) {
                const int n = warp_n * (BN / 4) + fn * 8;
                bf[fn][0] = __float_as_uint(bs[(k8 + tig)     * BST + n + gid]);
                bf[fn][1] = __float_as_uint(bs[(k8 + tig + 4) * BST + n + gid]);
            }
            #pragma unroll
            for (int fm = 0; fm < 4; fm++)
                #pragma unroll
                for (int fn = 0; fn < NF; fn++)
                    mma_tf32(acc[fm][fn], af[fm], bf[fn]);
        }

        // store staged tile into other buffer
        if (kt + 1 < KT) {
            float* asn = As[buf ^ 1];
            asn[ar * AST + ac + 0] = __uint_as_float(f2tf32(a_stg[0].x));
            asn[ar * AST + ac + 1] = __uint_as_float(f2tf32(a_stg[0].y));
            asn[ar * AST + ac + 2] = __uint_as_float(f2tf32(a_stg[0].z));
            asn[ar * AST + ac + 3] = __uint_as_float(f2tf32(a_stg[0].w));
            asn[(ar + 64) * AST + ac + 0] = __uint_as_float(f2tf32(a_stg[1].x));
            asn[(ar + 64) * AST + ac + 1] = __uint_as_float(f2tf32(a_stg[1].y));
            asn[(ar + 64) * AST + ac + 2] = __uint_as_float(f2tf32(a_stg[1].z));
            asn[(ar + 64) * AST + ac + 3] = __uint_as_float(f2tf32(a_stg[1].w));
            float* bsn = Bs[buf ^ 1];
            #pragma unroll
            for (int it = 0; it < BIT; it++) {
                bsn[br[it] * BST + bc[it] + 0] = __uint_as_float(f2tf32(b_stg[it].x));
                bsn[br[it] * BST + bc[it] + 1] = __uint_as_float(f2tf32(b_stg[it].y));
                bsn[br[it] * BST + bc[it] + 2] = __uint_as_float(f2tf32(b_stg[it].z));
                bsn[br[it] * BST + bc[it] + 3] = __uint_as_float(f2tf32(b_stg[it].w));
            }
            __syncthreads();
        }
    }

    // epilogue
    #pragma unroll
    for (int fm = 0; fm < 4; fm++) {
        const int r0 = row0 + warp_m * 64 + fm * 16 + gid;
        #pragma unroll
        for (int fn = 0; fn < NF; fn++) {
            const int c = col0 + warp_n * (BN / 4) + fn * 8 + tig * 2;
            #pragma unroll
            for (int half = 0; half < 2; half++) {
                const int r = r0 + half * 8;
                float2 v;
                v.x = acc[fm][fn][half * 2 + 0];
                v.y = acc[fm][fn][half * 2 + 1];
                if (flags & FLAG_BIAS) {
                    v.x += bias[c];
                    v.y += bias[c + 1];
                }
                if (flags & FLAG_GELU) {
                    v.x = gelu_exact(v.x);
                    v.y = gelu_exact(v.y);
                }
                if (flags & FLAG_RES) {
                    const float2 rr = *(const float2*)&res[(size_t)r * N + c];
                    v.x += rr.x;
                    v.y += rr.y;
                }
                *(float2*)&C[(size_t)r * N + c] = v;
            }
        }
    }
}

// ---------------- attention: flash-style, 1 thread = 1 query row ------
__global__ __launch_bounds__(128)
void attn_kernel(const float* __restrict__ qkv, float* __restrict__ o_out) {
    const int h   = blockIdx.y;
    const int qb  = blockIdx.x;
    const int tid = threadIdx.x;
    const int row = qb * 128 + tid;
    const float slope = exp2f(-0.5f * (float)(h + 1));

    __shared__ float Ks[32][DHEAD];
    __shared__ float Vs[32][DHEAD];

    float q[DHEAD];
    {
        const float* qp = qkv + (size_t)row * QKVW + h * DHEAD;
        #pragma unroll
        for (int i = 0; i < 16; i++) {
            float4 t = ((const float4*)qp)[i];
            q[4*i+0] = t.x * 0.125f;
            q[4*i+1] = t.y * 0.125f;
            q[4*i+2] = t.z * 0.125f;
            q[4*i+3] = t.w * 0.125f;
        }
    }

    float o[DHEAD];
    #pragma unroll
    for (int d = 0; d < DHEAD; d++) o[d] = 0.f;
    float m = -INFINITY, l = 0.f;

    const int ntiles = qb * 4 + 4;
    for (int kb = 0; kb < ntiles; kb++) {
        __syncthreads();
        #pragma unroll
        for (int it = 0; it < 16; it++) {
            int idx = tid + it * 128;
            int t = idx >> 6, d = idx & 63;
            size_t base = (size_t)(kb * 32 + t) * QKVW + h * DHEAD + d;
            Ks[t][d] = qkv[base + INNER];
            Vs[t][d] = qkv[base + 2 * INNER];
        }
        __syncthreads();

        if (kb * 32 <= row) {
            float s[32];
            float tmax = -INFINITY;
            #pragma unroll
            for (int t = 0; t < 32; t++) {
                int j = kb * 32 + t;
                float acc = 0.f;
                #pragma unroll
                for (int d = 0; d < DHEAD; d++) acc += q[d] * Ks[t][d];
                acc += slope * (float)j;
                s[t] = (j <= row) ? acc : -INFINITY;
                tmax = fmaxf(tmax, s[t]);
            }
            float mnew = fmaxf(m, tmax);
            float corr = __expf(m - mnew);
            l *= corr;
            #pragma unroll
            for (int d = 0; d < DHEAD; d++) o[d] *= corr;
            #pragma unroll
            for (int t = 0; t < 32; t++) {
                float p = __expf(s[t] - mnew);
                l += p;
                #pragma unroll
                for (int d = 0; d < DHEAD; d++) o[d] += p * Vs[t][d];
            }
            m = mnew;
        }
    }

    float inv = 1.0f / l;
    float* op = o_out + (size_t)row * INNER + h * DHEAD;
    #pragma unroll
    for (int i = 0; i < 16; i++) {
        float4 t;
        t.x = o[4*i+0] * inv;
        t.y = o[4*i+1] * inv;
        t.z = o[4*i+2] * inv;
        t.w = o[4*i+3] * inv;
        ((float4*)op)[i] = t;
    }
}

// ---------------- orchestration ----------------
extern "C" void kernel_launch(void* const* d_in, const int* in_sizes, int n_in,
                              void* d_out, int out_size) {
    const float* x      = (const float*)d_in[0];
    const float* qkv_w  = (const float*)d_in[1];
    const float* out_w  = (const float*)d_in[2];
    const float* attn_g = (const float*)d_in[3];
    const float* attn_b = (const float*)d_in[4];
    const float* ff_g   = (const float*)d_in[5];
    const float* ff_b   = (const float*)d_in[6];
    const float* ff_w1  = (const float*)d_in[7];
    const float* ff_b1  = (const float*)d_in[8];
    const float* ff_w2  = (const float*)d_in[9];
    const float* ff_b2  = (const float*)d_in[10];
    const float* fin_g  = (const float*)d_in[11];
    const float* fin_b  = (const float*)d_in[12];
    float* out = (float*)d_out;

    float *h, *y, *qkv, *o, *z;
    cudaGetSymbolAddress((void**)&h,   g_h);
    cudaGetSymbolAddress((void**)&y,   g_y);
    cudaGetSymbolAddress((void**)&qkv, g_qkv);
    cudaGetSymbolAddress((void**)&o,   g_o);
    cudaGetSymbolAddress((void**)&z,   g_z);

    cudaMemcpyAsync(h, x, (size_t)N_TOK * DIM * sizeof(float),
                    cudaMemcpyDeviceToDevice);

    for (int l = 0; l < LAYERS; l++) {
        // ---- attention block ----
        ln_kernel<<<N_TOK, 256>>>(h, attn_g + l * DIM, attn_b + l * DIM, y);
        mma_gemm<128><<<dim3(QKVW / 128, N_TOK / 128), 256>>>(
            y, qkv_w + (size_t)l * DIM * QKVW, nullptr, nullptr, qkv,
            N_TOK, QKVW, DIM, 0);
        attn_kernel<<<dim3(N_TOK / 128, HEADS), 128>>>(qkv, o);
        mma_gemm<64><<<dim3(DIM / 64, N_TOK / 128), 256>>>(
            o, out_w + (size_t)l * INNER * DIM, nullptr, h, h,
            N_TOK, DIM, INNER, FLAG_RES);
        // ---- feed-forward block ----
        ln_kernel<<<N_TOK, 256>>>(h, ff_g + l * DIM, ff_b + l * DIM, y);
        mma_gemm<128><<<dim3(FFDIM / 128, N_TOK / 128), 256>>>(
            y, ff_w1 + (size_t)l * DIM * FFDIM, ff_b1 + (size_t)l * FFDIM,
            nullptr, z, N_TOK, FFDIM, DIM, FLAG_BIAS | FLAG_GELU);
        mma_gemm<64><<<dim3(DIM / 64, N_TOK / 128), 256>>>(
            z, ff_w2 + (size_t)l * FFDIM * DIM, ff_b2 + (size_t)l * DIM,
            h, h, N_TOK, DIM, FFDIM, FLAG_BIAS | FLAG_RES);
    }
    ln_kernel<<<N_TOK, 256>>>(h, fin_g, fin_b, out);
}

// round 5
// speedup vs baseline: 2.9366x; 1.4702x over previous
#include <cuda_runtime.h>
#include <math.h>
#include <stdint.h>

#define N_TOK 2048
#define DIM   1024
#define HEADS 16
#define DHEAD 64
#define INNER 1024
#define FFDIM 4096
#define LAYERS 4
#define QKVW  (3*INNER)

// ---------------- scratch (no allocation allowed) ----------------
__device__ float g_h  [N_TOK * DIM];
__device__ float g_y  [N_TOK * DIM];
__device__ float g_qkv[N_TOK * QKVW];
__device__ float g_o  [N_TOK * INNER];
__device__ float g_z  [N_TOK * FFDIM];

__device__ __forceinline__ uint32_t f2tf32(float x) {
    uint32_t u;
    asm("cvt.rna.tf32.f32 %0, %1;" : "=r"(u) : "f"(x));
    return u;
}
__device__ __forceinline__ float gelu_exact(float x) {
    return 0.5f * x * (1.0f + erff(x * 0.70710678118654752f));
}
__device__ __forceinline__ void mma_tf32(float* c, const uint32_t* a, const uint32_t* b) {
    asm volatile(
        "mma.sync.aligned.m16n8k8.row.col.f32.tf32.tf32.f32 "
        "{%0,%1,%2,%3}, {%4,%5,%6,%7}, {%8,%9}, {%0,%1,%2,%3};"
        : "+f"(c[0]), "+f"(c[1]), "+f"(c[2]), "+f"(c[3])
        : "r"(a[0]), "r"(a[1]), "r"(a[2]), "r"(a[3]),
          "r"(b[0]), "r"(b[1]));
}

// ---------------- layernorm: one block per row ----------------
__global__ void ln_kernel(const float* __restrict__ in,
                          const float* __restrict__ g,
                          const float* __restrict__ b,
                          float* __restrict__ out) {
    int row = blockIdx.x;
    int tid = threadIdx.x;
    float4 v = ((const float4*)(in + (size_t)row * DIM))[tid];
    float s = v.x + v.y + v.z + v.w;
    float q = v.x*v.x + v.y*v.y + v.z*v.z + v.w*v.w;
    #pragma unroll
    for (int off = 16; off; off >>= 1) {
        s += __shfl_xor_sync(0xFFFFFFFFu, s, off);
        q += __shfl_xor_sync(0xFFFFFFFFu, q, off);
    }
    __shared__ float ss[8], qq[8];
    __shared__ float mean_s, rstd_s;
    int w = tid >> 5;
    if ((tid & 31) == 0) { ss[w] = s; qq[w] = q; }
    __syncthreads();
    if (tid == 0) {
        float S = 0.f, Q = 0.f;
        #pragma unroll
        for (int i = 0; i < 8; i++) { S += ss[i]; Q += qq[i]; }
        float mean = S * (1.0f / DIM);
        float var  = Q * (1.0f / DIM) - mean * mean;
        mean_s = mean;
        rstd_s = rsqrtf(var + 1e-5f);
    }
    __syncthreads();
    float mean = mean_s, rstd = rstd_s;
    float4 gg = ((const float4*)g)[tid];
    float4 bb = ((const float4*)b)[tid];
    float4 o;
    o.x = (v.x - mean) * rstd * gg.x + bb.x;
    o.y = (v.y - mean) * rstd * gg.y + bb.y;
    o.z = (v.z - mean) * rstd * gg.z + bb.z;
    o.w = (v.w - mean) * rstd * gg.w + bb.w;
    ((float4*)(out + (size_t)row * DIM))[tid] = o;
}

// ---------------- TF32 tensor-core GEMM (R3, known-good) ----------------
#define FLAG_BIAS 1
#define FLAG_GELU 2
#define FLAG_RES  4

template<int BN>
__global__ __launch_bounds__(256)
void mma_gemm(const float* __restrict__ A, const float* __restrict__ B,
              const float* __restrict__ bias, const float* __restrict__ res,
              float* __restrict__ C, int M, int N, int K, int flags) {
    constexpr int BM = 128, BK = 16;
    constexpr int NF = BN / 32;
    constexpr int AST = BK + 4;
    constexpr int BST = BN + 8;
    constexpr int BF4 = BN / 4;
    constexpr int BIT = (BK * BF4) / 256;

    __shared__ float As[2][BM * AST];
    __shared__ float Bs[2][BK * BST];

    const int tid  = threadIdx.x;
    const int lane = tid & 31;
    const int wid  = tid >> 5;
    const int gid  = lane >> 2;
    const int tig  = lane & 3;
    const int warp_m = wid >> 2;
    const int warp_n = wid & 3;
    const int row0 = blockIdx.y * BM;
    const int col0 = blockIdx.x * BN;

    const int ar = tid >> 2;
    const int ac = (tid & 3) << 2;
    int br[BIT], bc[BIT];
    #pragma unroll
    for (int it = 0; it < BIT; it++) {
        int idx = tid + it * 256;
        br[it] = idx / BF4;
        bc[it] = (idx % BF4) << 2;
    }

    float acc[4][NF][4];
    #pragma unroll
    for (int i = 0; i < 4; i++)
        #pragma unroll
        for (int j = 0; j < NF; j++)
            #pragma unroll
            for (int r = 0; r < 4; r++) acc[i][j][r] = 0.f;

    float4 a_stg[2];
    float4 b_stg[BIT];

    const int KT = K / BK;

    a_stg[0] = *(const float4*)(A + (size_t)(row0 + ar) * K + ac);
    a_stg[1] = *(const float4*)(A + (size_t)(row0 + ar + 64) * K + ac);
    #pragma unroll
    for (int it = 0; it < BIT; it++)
        b_stg[it] = *(const float4*)(B + (size_t)br[it] * N + col0 + bc[it]);
    {
        float* as = As[0];
        as[ar * AST + ac + 0] = __uint_as_float(f2tf32(a_stg[0].x));
        as[ar * AST + ac + 1] = __uint_as_float(f2tf32(a_stg[0].y));
        as[ar * AST + ac + 2] = __uint_as_float(f2tf32(a_stg[0].z));
        as[ar * AST + ac + 3] = __uint_as_float(f2tf32(a_stg[0].w));
        as[(ar + 64) * AST + ac + 0] = __uint_as_float(f2tf32(a_stg[1].x));
        as[(ar + 64) * AST + ac + 1] = __uint_as_float(f2tf32(a_stg[1].y));
        as[(ar + 64) * AST + ac + 2] = __uint_as_float(f2tf32(a_stg[1].z));
        as[(ar + 64) * AST + ac + 3] = __uint_as_float(f2tf32(a_stg[1].w));
        float* bs = Bs[0];
        #pragma unroll
        for (int it = 0; it < BIT; it++) {
            bs[br[it] * BST + bc[it] + 0] = __uint_as_float(f2tf32(b_stg[it].x));
            bs[br[it] * BST + bc[it] + 1] = __uint_as_float(f2tf32(b_stg[it].y));
            bs[br[it] * BST + bc[it] + 2] = __uint_as_float(f2tf32(b_stg[it].z));
            bs[br[it] * BST + bc[it] + 3] = __uint_as_float(f2tf32(b_stg[it].w));
        }
    }
    __syncthreads();

    for (int kt = 0; kt < KT; kt++) {
        const int buf = kt & 1;
        if (kt + 1 < KT) {
            const int k0 = (kt + 1) * BK;
            a_stg[0] = *(const float4*)(A + (size_t)(row0 + ar) * K + k0 + ac);
            a_stg[1] = *(const float4*)(A + (size_t)(row0 + ar + 64) * K + k0 + ac);
            #pragma unroll
            for (int it = 0; it < BIT; it++)
                b_stg[it] = *(const float4*)(B + (size_t)(k0 + br[it]) * N + col0 + bc[it]);
        }

        const float* as = As[buf];
        const float* bs = Bs[buf];
        #pragma unroll
        for (int ks = 0; ks < 2; ks++) {
            const int k8 = ks * 8;
            uint32_t af[4][4];
            #pragma unroll
            for (int fm = 0; fm < 4; fm++) {
                const int m = warp_m * 64 + fm * 16;
                af[fm][0] = __float_as_uint(as[(m + gid)     * AST + k8 + tig]);
                af[fm][1] = __float_as_uint(as[(m + gid + 8) * AST + k8 + tig]);
                af[fm][2] = __float_as_uint(as[(m + gid)     * AST + k8 + tig + 4]);
                af[fm][3] = __float_as_uint(as[(m + gid + 8) * AST + k8 + tig + 4]);
            }
            uint32_t bf[NF][2];
            #pragma unroll
            for (int fn = 0; fn < NF; fn++) {
                const int n = warp_n * (BN / 4) + fn * 8;
                bf[fn][0] = __float_as_uint(bs[(k8 + tig)     * BST + n + gid]);
                bf[fn][1] = __float_as_uint(bs[(k8 + tig + 4) * BST + n + gid]);
            }
            #pragma unroll
            for (int fm = 0; fm < 4; fm++)
                #pragma unroll
                for (int fn = 0; fn < NF; fn++)
                    mma_tf32(acc[fm][fn], af[fm], bf[fn]);
        }

        if (kt + 1 < KT) {
            float* asn = As[buf ^ 1];
            asn[ar * AST + ac + 0] = __uint_as_float(f2tf32(a_stg[0].x));
            asn[ar * AST + ac + 1] = __uint_as_float(f2tf32(a_stg[0].y));
            asn[ar * AST + ac + 2] = __uint_as_float(f2tf32(a_stg[0].z));
            asn[ar * AST + ac + 3] = __uint_as_float(f2tf32(a_stg[0].w));
            asn[(ar + 64) * AST + ac + 0] = __uint_as_float(f2tf32(a_stg[1].x));
            asn[(ar + 64) * AST + ac + 1] = __uint_as_float(f2tf32(a_stg[1].y));
            asn[(ar + 64) * AST + ac + 2] = __uint_as_float(f2tf32(a_stg[1].z));
            asn[(ar + 64) * AST + ac + 3] = __uint_as_float(f2tf32(a_stg[1].w));
            float* bsn = Bs[buf ^ 1];
            #pragma unroll
            for (int it = 0; it < BIT; it++) {
                bsn[br[it] * BST + bc[it] + 0] = __uint_as_float(f2tf32(b_stg[it].x));
                bsn[br[it] * BST + bc[it] + 1] = __uint_as_float(f2tf32(b_stg[it].y));
                bsn[br[it] * BST + bc[it] + 2] = __uint_as_float(f2tf32(b_stg[it].z));
                bsn[br[it] * BST + bc[it] + 3] = __uint_as_float(f2tf32(b_stg[it].w));
            }
            __syncthreads();
        }
    }

    #pragma unroll
    for (int fm = 0; fm < 4; fm++) {
        const int r0 = row0 + warp_m * 64 + fm * 16 + gid;
        #pragma unroll
        for (int fn = 0; fn < NF; fn++) {
            const int c = col0 + warp_n * (BN / 4) + fn * 8 + tig * 2;
            #pragma unroll
            for (int half = 0; half < 2; half++) {
                const int r = r0 + half * 8;
                float2 v;
                v.x = acc[fm][fn][half * 2 + 0];
                v.y = acc[fm][fn][half * 2 + 1];
                if (flags & FLAG_BIAS) {
                    v.x += bias[c];
                    v.y += bias[c + 1];
                }
                if (flags & FLAG_GELU) {
                    v.x = gelu_exact(v.x);
                    v.y = gelu_exact(v.y);
                }
                if (flags & FLAG_RES) {
                    const float2 rr = *(const float2*)&res[(size_t)r * N + c];
                    v.x += rr.x;
                    v.y += rr.y;
                }
                *(float2*)&C[(size_t)r * N + c] = v;
            }
        }
    }
}

// ---------------- flash attention with mma.sync tf32 ----------------
// grid (qtiles=32, heads=16), block 128 (4 warps). Warp w owns rows
// qt*64 + w*16 .. +15 via m16n8k8 fragments. KV tiles of 64 keys staged
// in smem in B-fragment-major order (tf32-rounded at store).
__global__ __launch_bounds__(128)
void attn_mma_kernel(const float* __restrict__ qkv, float* __restrict__ o_out) {
    const int h    = blockIdx.y;
    const int qt   = blockIdx.x;
    const int tid  = threadIdx.x;
    const int w    = tid >> 5;
    const int lane = tid & 31;
    const int gid  = lane >> 2;
    const int tig  = lane & 3;
    const float slope = exp2f(-0.5f * (float)(h + 1));

    // frag-major: [blk = nblk*8 + k8][lane][2 regs]
    __shared__ float Ks[64 * 32 * 2];
    __shared__ float Vs[64 * 32 * 2];

    const int rowA = qt * 64 + w * 16 + gid;
    const int rowB = rowA + 8;

    // Q fragments (scaled, tf32) — resident in registers for the whole block
    uint32_t qf[8][4];
    {
        const float* qa = qkv + (size_t)rowA * QKVW + h * DHEAD;
        const float* qb = qkv + (size_t)rowB * QKVW + h * DHEAD;
        #pragma unroll
        for (int k8 = 0; k8 < 8; k8++) {
            qf[k8][0] = f2tf32(qa[k8 * 8 + tig]     * 0.125f);
            qf[k8][1] = f2tf32(qb[k8 * 8 + tig]     * 0.125f);
            qf[k8][2] = f2tf32(qa[k8 * 8 + tig + 4] * 0.125f);
            qf[k8][3] = f2tf32(qb[k8 * 8 + tig + 4] * 0.125f);
        }
    }

    float o[8][4];
    #pragma unroll
    for (int i = 0; i < 8; i++)
        #pragma unroll
        for (int r = 0; r < 4; r++) o[i][r] = 0.f;
    float mA = -INFINITY, mB = -INFINITY, lA = 0.f, lB = 0.f;

    for (int kt = 0; kt <= qt; kt++) {
        __syncthreads();
        // ---- stage K/V tile (64 keys x 64 dims), frag-major, tf32 ----
        #pragma unroll
        for (int i = 0; i < 8; i++) {
            const int idx = tid + i * 128;
            const int key = idx >> 4;
            const int d0  = (idx & 15) << 2;
            const float* kp = qkv + (size_t)(kt * 64 + key) * QKVW + INNER + h * DHEAD + d0;
            float4 kv = *(const float4*)kp;
            float4 vv = *(const float4*)(kp + INNER);
            // K as B-operand of S: k-dim=d, n-dim=key
            {
                const int base = ((((key >> 3) * 8 + (d0 >> 3)) * 32 + (key & 7) * 4) << 1)
                                 + ((d0 & 7) >> 2);
                Ks[base + 0] = __uint_as_float(f2tf32(kv.x));
                Ks[base + 2] = __uint_as_float(f2tf32(kv.y));
                Ks[base + 4] = __uint_as_float(f2tf32(kv.z));
                Ks[base + 6] = __uint_as_float(f2tf32(kv.w));
            }
            // V as B-operand of AV: k-dim=key, n-dim=d
            {
                const int base = ((((d0 >> 3) * 8 + (key >> 3)) * 32 + (d0 & 7) * 4 + (key & 3)) << 1)
                                 + ((key & 7) >> 2);
                Vs[base + 0]  = __uint_as_float(f2tf32(vv.x));
                Vs[base + 8]  = __uint_as_float(f2tf32(vv.y));
                Vs[base + 16] = __uint_as_float(f2tf32(vv.z));
                Vs[base + 24] = __uint_as_float(f2tf32(vv.w));
            }
        }
        __syncthreads();

        // ---- S = Q K^T : m16 x n64 x k64 ----
        float s[8][4];
        #pragma unroll
        for (int nb = 0; nb < 8; nb++) {
            s[nb][0] = s[nb][1] = s[nb][2] = s[nb][3] = 0.f;
            #pragma unroll
            for (int k8 = 0; k8 < 8; k8++) {
                const float2 b = *(const float2*)&Ks[((nb * 8 + k8) * 32 + lane) << 1];
                mma_tf32(s[nb], qf[k8], (const uint32_t*)&b);
            }
        }

        // ---- ALiBi + causal mask + row max ----
        const int cb = kt * 64;
        float tmA = -INFINITY, tmB = -INFINITY;
        #pragma unroll
        for (int nb = 0; nb < 8; nb++) {
            const int c0 = cb + nb * 8 + 2 * tig;
            s[nb][0] += slope * (float)c0;
            s[nb][1] += slope * (float)(c0 + 1);
            s[nb][2] += slope * (float)c0;
            s[nb][3] += slope * (float)(c0 + 1);
            if (kt == qt) {
                if (c0     > rowA) s[nb][0] = -INFINITY;
                if (c0 + 1 > rowA) s[nb][1] = -INFINITY;
                if (c0     > rowB) s[nb][2] = -INFINITY;
                if (c0 + 1 > rowB) s[nb][3] = -INFINITY;
            }
            tmA = fmaxf(tmA, fmaxf(s[nb][0], s[nb][1]));
            tmB = fmaxf(tmB, fmaxf(s[nb][2], s[nb][3]));
        }
        tmA = fmaxf(tmA, __shfl_xor_sync(0xFFFFFFFFu, tmA, 1));
        tmA = fmaxf(tmA, __shfl_xor_sync(0xFFFFFFFFu, tmA, 2));
        tmB = fmaxf(tmB, __shfl_xor_sync(0xFFFFFFFFu, tmB, 1));
        tmB = fmaxf(tmB, __shfl_xor_sync(0xFFFFFFFFu, tmB, 2));

        const float mnA = fmaxf(mA, tmA);
        const float mnB = fmaxf(mB, tmB);
        const float cA = __expf(mA - mnA);
        const float cB = __expf(mB - mnB);
        lA *= cA;
        lB *= cB;
        #pragma unroll
        for (int nb = 0; nb < 8; nb++) {
            o[nb][0] *= cA; o[nb][1] *= cA;
            o[nb][2] *= cB; o[nb][3] *= cB;
        }

        // ---- P = exp(S - m), accumulate l ----
        #pragma unroll
        for (int nb = 0; nb < 8; nb++) {
            s[nb][0] = __expf(s[nb][0] - mnA);
            s[nb][1] = __expf(s[nb][1] - mnA);
            s[nb][2] = __expf(s[nb][2] - mnB);
            s[nb][3] = __expf(s[nb][3] - mnB);
            lA += s[nb][0] + s[nb][1];
            lB += s[nb][2] + s[nb][3];
        }

        // ---- C-frag -> A-frag conversion via shuffles ----
        const int src1 = gid * 4 + (tig >> 1);
        const int src2 = src1 + 2;
        const bool odd = (tig & 1);
        uint32_t pa[8][4];
        #pragma unroll
        for (int k8 = 0; k8 < 8; k8++) {
            float v0 = __shfl_sync(0xFFFFFFFFu, s[k8][0], src1);
            float v1 = __shfl_sync(0xFFFFFFFFu, s[k8][1], src1);
            float v2 = __shfl_sync(0xFFFFFFFFu, s[k8][2], src1);
            float v3 = __shfl_sync(0xFFFFFFFFu, s[k8][3], src1);
            float u0 = __shfl_sync(0xFFFFFFFFu, s[k8][0], src2);
            float u1 = __shfl_sync(0xFFFFFFFFu, s[k8][1], src2);
            float u2 = __shfl_sync(0xFFFFFFFFu, s[k8][2], src2);
            float u3 = __shfl_sync(0xFFFFFFFFu, s[k8][3], src2);
            pa[k8][0] = f2tf32(odd ? v1 : v0);
            pa[k8][1] = f2tf32(odd ? v3 : v2);
            pa[k8][2] = f2tf32(odd ? u1 : u0);
            pa[k8][3] = f2tf32(odd ? u3 : u2);
        }

        // ---- O += P V : m16 x n64(d) x k64(keys) ----
        #pragma unroll
        for (int nb = 0; nb < 8; nb++) {
            #pragma unroll
            for (int k8 = 0; k8 < 8; k8++) {
                const float2 b = *(const float2*)&Vs[((nb * 8 + k8) * 32 + lane) << 1];
                mma_tf32(o[nb], pa[k8], (const uint32_t*)&b);
            }
        }

        mA = mnA;
        mB = mnB;
    }

    lA += __shfl_xor_sync(0xFFFFFFFFu, lA, 1);
    lA += __shfl_xor_sync(0xFFFFFFFFu, lA, 2);
    lB += __shfl_xor_sync(0xFFFFFFFFu, lB, 1);
    lB += __shfl_xor_sync(0xFFFFFFFFu, lB, 2);
    const float invA = 1.0f / lA;
    const float invB = 1.0f / lB;

    float* oa = o_out + (size_t)rowA * INNER + h * DHEAD;
    float* ob = o_out + (size_t)rowB * INNER + h * DHEAD;
    #pragma unroll
    for (int nb = 0; nb < 8; nb++) {
        const int c = nb * 8 + 2 * tig;
        float2 va; va.x = o[nb][0] * invA; va.y = o[nb][1] * invA;
        float2 vb; vb.x = o[nb][2] * invB; vb.y = o[nb][3] * invB;
        *(float2*)(oa + c) = va;
        *(float2*)(ob + c) = vb;
    }
}

// ---------------- orchestration ----------------
extern "C" void kernel_launch(void* const* d_in, const int* in_sizes, int n_in,
                              void* d_out, int out_size) {
    const float* x      = (const float*)d_in[0];
    const float* qkv_w  = (const float*)d_in[1];
    const float* out_w  = (const float*)d_in[2];
    const float* attn_g = (const float*)d_in[3];
    const float* attn_b = (const float*)d_in[4];
    const float* ff_g   = (const float*)d_in[5];
    const float* ff_b   = (const float*)d_in[6];
    const float* ff_w1  = (const float*)d_in[7];
    const float* ff_b1  = (const float*)d_in[8];
    const float* ff_w2  = (const float*)d_in[9];
    const float* ff_b2  = (const float*)d_in[10];
    const float* fin_g  = (const float*)d_in[11];
    const float* fin_b  = (const float*)d_in[12];
    float* out = (float*)d_out;

    float *h, *y, *qkv, *o, *z;
    cudaGetSymbolAddress((void**)&h,   g_h);
    cudaGetSymbolAddress((void**)&y,   g_y);
    cudaGetSymbolAddress((void**)&qkv, g_qkv);
    cudaGetSymbolAddress((void**)&o,   g_o);
    cudaGetSymbolAddress((void**)&z,   g_z);

    cudaMemcpyAsync(h, x, (size_t)N_TOK * DIM * sizeof(float),
                    cudaMemcpyDeviceToDevice);

    for (int l = 0; l < LAYERS; l++) {
        // ---- attention block ----
        ln_kernel<<<N_TOK, 256>>>(h, attn_g + l * DIM, attn_b + l * DIM, y);
        mma_gemm<128><<<dim3(QKVW / 128, N_TOK / 128), 256>>>(
            y, qkv_w + (size_t)l * DIM * QKVW, nullptr, nullptr, qkv,
            N_TOK, QKVW, DIM, 0);
        attn_mma_kernel<<<dim3(N_TOK / 64, HEADS), 128>>>(qkv, o);
        mma_gemm<64><<<dim3(DIM / 64, N_TOK / 128), 256>>>(
            o, out_w + (size_t)l * INNER * DIM, nullptr, h, h,
            N_TOK, DIM, INNER, FLAG_RES);
        // ---- feed-forward block ----
        ln_kernel<<<N_TOK, 256>>>(h, ff_g + l * DIM, ff_b + l * DIM, y);
        mma_gemm<128><<<dim3(FFDIM / 128, N_TOK / 128), 256>>>(
            y, ff_w1 + (size_t)l * DIM * FFDIM, ff_b1 + (size_t)l * FFDIM,
            nullptr, z, N_TOK, FFDIM, DIM, FLAG_BIAS | FLAG_GELU);
        mma_gemm<64><<<dim3(DIM / 64, N_TOK / 128), 256>>>(
            z, ff_w2 + (size_t)l * FFDIM * DIM, ff_b2 + (size_t)l * DIM,
            h, h, N_TOK, DIM, FFDIM, FLAG_BIAS | FLAG_RES);
    }
    ln_kernel<<<N_TOK, 256>>>(h, fin_g, fin_b, out);
}

// round 6
// speedup vs baseline: 3.3944x; 1.1559x over previous
#include <cuda_runtime.h>
#include <math.h>
#include <stdint.h>

#define N_TOK 2048
#define DIM   1024
#define HEADS 16
#define DHEAD 64
#define INNER 1024
#define FFDIM 4096
#define LAYERS 4
#define QKVW  (3*INNER)

// ---------------- scratch (no allocation allowed) ----------------
__device__ float g_h  [N_TOK * DIM];
__device__ float g_y  [N_TOK * DIM];
__device__ float g_qkv[N_TOK * QKVW];
__device__ float g_o  [N_TOK * INNER];
__device__ float g_z  [N_TOK * FFDIM];
// transposed + tf32-rounded weights, [N][K] row-major
__device__ float g_qkvT[LAYERS * QKVW * DIM];
__device__ float g_outT[LAYERS * DIM * INNER];
__device__ float g_ff1T[LAYERS * FFDIM * DIM];
__device__ float g_ff2T[LAYERS * DIM * FFDIM];

__device__ __forceinline__ uint32_t f2tf32(float x) {
    uint32_t u;
    asm("cvt.rna.tf32.f32 %0, %1;" : "=r"(u) : "f"(x));
    return u;
}
__device__ __forceinline__ float rnd_tf32(float x) {
    return __uint_as_float(f2tf32(x));
}
__device__ __forceinline__ float gelu_exact(float x) {
    return 0.5f * x * (1.0f + erff(x * 0.70710678118654752f));
}
__device__ __forceinline__ uint32_t smem_u32(const void* p) {
    uint32_t a;
    asm("{ .reg .u64 t; cvta.to.shared.u64 t, %1; cvt.u32.u64 %0, t; }"
        : "=r"(a) : "l"(p));
    return a;
}
__device__ __forceinline__ void mma_tf32(float* c, const uint32_t* a, const uint32_t* b) {
    asm volatile(
        "mma.sync.aligned.m16n8k8.row.col.f32.tf32.tf32.f32 "
        "{%0,%1,%2,%3}, {%4,%5,%6,%7}, {%8,%9}, {%0,%1,%2,%3};"
        : "+f"(c[0]), "+f"(c[1]), "+f"(c[2]), "+f"(c[3])
        : "r"(a[0]), "r"(a[1]), "r"(a[2]), "r"(a[3]),
          "r"(b[0]), "r"(b[1]));
}
#define LDSM_X4(r0, r1, r2, r3, addr) \
    asm volatile("ldmatrix.sync.aligned.m8n8.x4.shared.b16 {%0,%1,%2,%3}, [%4];" \
                 : "=r"(r0), "=r"(r1), "=r"(r2), "=r"(r3) : "r"(addr))
__device__ __forceinline__ void cp_async16(uint32_t dst, const void* src) {
    asm volatile("cp.async.ca.shared.global [%0], [%1], 16;" :: "r"(dst), "l"(src));
}
#define CP_COMMIT() asm volatile("cp.async.commit_group;" ::: "memory")
#define CP_WAIT(n)  asm volatile("cp.async.wait_group %0;" :: "n"(n) : "memory")

// ---------------- layernorm: one block per row ----------------
template<bool ROUND>
__global__ void ln_kernel(const float* __restrict__ in,
                          const float* __restrict__ g,
                          const float* __restrict__ b,
                          float* __restrict__ out) {
    int row = blockIdx.x;
    int tid = threadIdx.x;
    float4 v = ((const float4*)(in + (size_t)row * DIM))[tid];
    float s = v.x + v.y + v.z + v.w;
    float q = v.x*v.x + v.y*v.y + v.z*v.z + v.w*v.w;
    #pragma unroll
    for (int off = 16; off; off >>= 1) {
        s += __shfl_xor_sync(0xFFFFFFFFu, s, off);
        q += __shfl_xor_sync(0xFFFFFFFFu, q, off);
    }
    __shared__ float ss[8], qq[8];
    __shared__ float mean_s, rstd_s;
    int w = tid >> 5;
    if ((tid & 31) == 0) { ss[w] = s; qq[w] = q; }
    __syncthreads();
    if (tid == 0) {
        float S = 0.f, Q = 0.f;
        #pragma unroll
        for (int i = 0; i < 8; i++) { S += ss[i]; Q += qq[i]; }
        float mean = S * (1.0f / DIM);
        float var  = Q * (1.0f / DIM) - mean * mean;
        mean_s = mean;
        rstd_s = rsqrtf(var + 1e-5f);
    }
    __syncthreads();
    float mean = mean_s, rstd = rstd_s;
    float4 gg = ((const float4*)g)[tid];
    float4 bb = ((const float4*)b)[tid];
    float4 o;
    o.x = (v.x - mean) * rstd * gg.x + bb.x;
    o.y = (v.y - mean) * rstd * gg.y + bb.y;
    o.z = (v.z - mean) * rstd * gg.z + bb.z;
    o.w = (v.w - mean) * rstd * gg.w + bb.w;
    if (ROUND) {
        o.x = rnd_tf32(o.x); o.y = rnd_tf32(o.y);
        o.z = rnd_tf32(o.z); o.w = rnd_tf32(o.w);
    }
    ((float4*)(out + (size_t)row * DIM))[tid] = o;
}

// ---------------- weight transpose [L][K][N] -> [L][N][K], tf32-rounded ----
__global__ void transpose_k(const float* __restrict__ in, float* __restrict__ out,
                            int K, int N) {
    __shared__ float t[32][33];
    int z = blockIdx.z;
    const float* ip = in + (size_t)z * K * N;
    float* op = out + (size_t)z * K * N;
    int k0 = blockIdx.y * 32, n0 = blockIdx.x * 32;
    int tx = threadIdx.x, ty = threadIdx.y;  // 32 x 8
    #pragma unroll
    for (int j = 0; j < 32; j += 8)
        t[ty + j][tx] = ip[(size_t)(k0 + ty + j) * N + n0 + tx];
    __syncthreads();
    #pragma unroll
    for (int j = 0; j < 32; j += 8)
        op[(size_t)(n0 + ty + j) * K + k0 + tx] = rnd_tf32(t[tx][ty + j]);
}

// ---------------- TF32 GEMM v2: ldmatrix + cp.async 3-stage --------------
// C[M,N] = A[M,K] @ BT[N,K]^T  (+bias)(gelu)(+res)(round)
// BM=128, BN in {128,64}; warp tile 64x32; BK=16. Inputs pre-rounded to tf32.
#define FLAG_BIAS  1
#define FLAG_GELU  2
#define FLAG_RES   4
#define FLAG_ROUND 8
#define GSTAGES 3

template<int BN>
__global__ __launch_bounds__(BN * 2)
void mma_gemm(const float* __restrict__ A, const float* __restrict__ BT,
              const float* __restrict__ bias, const float* __restrict__ res,
              float* __restrict__ C, int M, int N, int K, int flags) {
    constexpr int THREADS = BN * 2;          // 256 or 128
    constexpr int BM = 128, BK = 16;
    constexpr int RST = 20;                  // padded row stride (floats)
    constexpr int SA = BM * RST;             // 2560 floats
    constexpr int SB = BN * RST;
    constexpr int STAGE = SA + SB;           // floats
    constexpr int WN = BN / 32;              // warps across N (4 or 2)
    constexpr int AIT = (BM * 4) / THREADS;  // A 16B-chunks per thread
    constexpr int BIT = (BN * 4) / THREADS;  // B 16B-chunks per thread

    extern __shared__ float sm[];
    const uint32_t sb0 = smem_u32(sm);

    const int tid  = threadIdx.x;
    const int lane = tid & 31;
    const int wid  = tid >> 5;
    const int gid  = lane >> 2;
    const int tig  = lane & 3;
    const int warp_m = wid / WN;
    const int warp_n = wid % WN;
    const int row0 = blockIdx.y * BM;
    const int col0 = blockIdx.x * BN;

    // lane-invariant parts of ldmatrix addresses (bytes)
    const uint32_t aLane = ((warp_m * 64 + (lane & 15)) * RST + ((lane >> 4) << 2)) * 4;
    const uint32_t bLane = SA * 4 + ((warp_n * 32 + (lane & 7)) * RST + ((lane >> 3) << 2)) * 4;

    float acc[4][4][4];
    #pragma unroll
    for (int i = 0; i < 4; i++)
        #pragma unroll
        for (int j = 0; j < 4; j++)
            #pragma unroll
            for (int r = 0; r < 4; r++) acc[i][j][r] = 0.f;

    auto load_stage = [&](int s, int k0) {
        const uint32_t base = sb0 + s * (STAGE * 4);
        #pragma unroll
        for (int i = 0; i < AIT; i++) {
            const int f = tid + i * THREADS;
            const int r = f >> 2, c4 = (f & 3) << 2;
            cp_async16(base + (r * RST + c4) * 4,
                       A + (size_t)(row0 + r) * K + k0 + c4);
        }
        #pragma unroll
        for (int i = 0; i < BIT; i++) {
            const int f = tid + i * THREADS;
            const int n = f >> 2, c4 = (f & 3) << 2;
            cp_async16(base + SA * 4 + (n * RST + c4) * 4,
                       BT + (size_t)(col0 + n) * K + k0 + c4);
        }
    };

    const int KT = K / BK;
    load_stage(0, 0);
    CP_COMMIT();
    load_stage(1, BK);
    CP_COMMIT();

    for (int kt = 0; kt < KT; kt++) {
        const int s = kt % GSTAGES;
        CP_WAIT(1);
        __syncthreads();

        if (kt + 2 < KT) load_stage((kt + 2) % GSTAGES, (kt + 2) * BK);
        CP_COMMIT();

        const uint32_t base = sb0 + s * (STAGE * 4);
        const uint32_t aW = base + aLane;
        const uint32_t bW = base + bLane;

        uint32_t af[4][2][4];
        #pragma unroll
        for (int fm = 0; fm < 4; fm++)
            #pragma unroll
            for (int k8 = 0; k8 < 2; k8++)
                LDSM_X4(af[fm][k8][0], af[fm][k8][1], af[fm][k8][2], af[fm][k8][3],
                        aW + fm * (16 * RST * 4) + k8 * 32);
        uint32_t bf[4][4];   // [fn][b0k0,b1k0,b0k1,b1k1]
        #pragma unroll
        for (int fn = 0; fn < 4; fn++)
            LDSM_X4(bf[fn][0], bf[fn][1], bf[fn][2], bf[fn][3],
                    bW + fn * (8 * RST * 4));

        #pragma unroll
        for (int k8 = 0; k8 < 2; k8++)
            #pragma unroll
            for (int fm = 0; fm < 4; fm++)
                #pragma unroll
                for (int fn = 0; fn < 4; fn++)
                    mma_tf32(acc[fm][fn], af[fm][k8], &bf[fn][k8 * 2]);
    }

    // epilogue
    #pragma unroll
    for (int fm = 0; fm < 4; fm++) {
        const int r0 = row0 + warp_m * 64 + fm * 16 + gid;
        #pragma unroll
        for (int fn = 0; fn < 4; fn++) {
            const int c = col0 + warp_n * 32 + fn * 8 + tig * 2;
            #pragma unroll
            for (int half = 0; half < 2; half++) {
                const int r = r0 + half * 8;
                float2 v;
                v.x = acc[fm][fn][half * 2 + 0];
                v.y = acc[fm][fn][half * 2 + 1];
                if (flags & FLAG_BIAS) {
                    v.x += bias[c];
                    v.y += bias[c + 1];
                }
                if (flags & FLAG_GELU) {
                    v.x = gelu_exact(v.x);
                    v.y = gelu_exact(v.y);
                }
                if (flags & FLAG_RES) {
                    const float2 rr = *(const float2*)&res[(size_t)r * N + c];
                    v.x += rr.x;
                    v.y += rr.y;
                }
                if (flags & FLAG_ROUND) {
                    v.x = rnd_tf32(v.x);
                    v.y = rnd_tf32(v.y);
                }
                *(float2*)&C[(size_t)r * N + c] = v;
            }
        }
    }
}

// ---------------- flash attention with mma.sync tf32 (R5, known-good) ----
__global__ __launch_bounds__(128)
void attn_mma_kernel(const float* __restrict__ qkv, float* __restrict__ o_out) {
    const int h    = blockIdx.y;
    const int qt   = blockIdx.x;
    const int tid  = threadIdx.x;
    const int w    = tid >> 5;
    const int lane = tid & 31;
    const int gid  = lane >> 2;
    const int tig  = lane & 3;
    const float slope = exp2f(-0.5f * (float)(h + 1));

    __shared__ float Ks[64 * 32 * 2];
    __shared__ float Vs[64 * 32 * 2];

    const int rowA = qt * 64 + w * 16 + gid;
    const int rowB = rowA + 8;

    uint32_t qf[8][4];
    {
        const float* qa = qkv + (size_t)rowA * QKVW + h * DHEAD;
        const float* qb = qkv + (size_t)rowB * QKVW + h * DHEAD;
        #pragma unroll
        for (int k8 = 0; k8 < 8; k8++) {
            qf[k8][0] = f2tf32(qa[k8 * 8 + tig]     * 0.125f);
            qf[k8][1] = f2tf32(qb[k8 * 8 + tig]     * 0.125f);
            qf[k8][2] = f2tf32(qa[k8 * 8 + tig + 4] * 0.125f);
            qf[k8][3] = f2tf32(qb[k8 * 8 + tig + 4] * 0.125f);
        }
    }

    float o[8][4];
    #pragma unroll
    for (int i = 0; i < 8; i++)
        #pragma unroll
        for (int r = 0; r < 4; r++) o[i][r] = 0.f;
    float mA = -INFINITY, mB = -INFINITY, lA = 0.f, lB = 0.f;

    for (int kt = 0; kt <= qt; kt++) {
        __syncthreads();
        #pragma unroll
        for (int i = 0; i < 8; i++) {
            const int idx = tid + i * 128;
            const int key = idx >> 4;
            const int d0  = (idx & 15) << 2;
            const float* kp = qkv + (size_t)(kt * 64 + key) * QKVW + INNER + h * DHEAD + d0;
            float4 kv = *(const float4*)kp;
            float4 vv = *(const float4*)(kp + INNER);
            {
                const int base = ((((key >> 3) * 8 + (d0 >> 3)) * 32 + (key & 7) * 4) << 1)
                                 + ((d0 & 7) >> 2);
                Ks[base + 0] = __uint_as_float(f2tf32(kv.x));
                Ks[base + 2] = __uint_as_float(f2tf32(kv.y));
                Ks[base + 4] = __uint_as_float(f2tf32(kv.z));
                Ks[base + 6] = __uint_as_float(f2tf32(kv.w));
            }
            {
                const int base = ((((d0 >> 3) * 8 + (key >> 3)) * 32 + (d0 & 7) * 4 + (key & 3)) << 1)
                                 + ((key & 7) >> 2);
                Vs[base + 0]  = __uint_as_float(f2tf32(vv.x));
                Vs[base + 8]  = __uint_as_float(f2tf32(vv.y));
                Vs[base + 16] = __uint_as_float(f2tf32(vv.z));
                Vs[base + 24] = __uint_as_float(f2tf32(vv.w));
            }
        }
        __syncthreads();

        float s[8][4];
        #pragma unroll
        for (int nb = 0; nb < 8; nb++) {
            s[nb][0] = s[nb][1] = s[nb][2] = s[nb][3] = 0.f;
            #pragma unroll
            for (int k8 = 0; k8 < 8; k8++) {
                const float2 b = *(const float2*)&Ks[((nb * 8 + k8) * 32 + lane) << 1];
                mma_tf32(s[nb], qf[k8], (const uint32_t*)&b);
            }
        }

        const int cb = kt * 64;
        float tmA = -INFINITY, tmB = -INFINITY;
        #pragma unroll
        for (int nb = 0; nb < 8; nb++) {
            const int c0 = cb + nb * 8 + 2 * tig;
            s[nb][0] += slope * (float)c0;
            s[nb][1] += slope * (float)(c0 + 1);
            s[nb][2] += slope * (float)c0;
            s[nb][3] += slope * (float)(c0 + 1);
            if (kt == qt) {
                if (c0     > rowA) s[nb][0] = -INFINITY;
                if (c0 + 1 > rowA) s[nb][1] = -INFINITY;
                if (c0     > rowB) s[nb][2] = -INFINITY;
                if (c0 + 1 > rowB) s[nb][3] = -INFINITY;
            }
            tmA = fmaxf(tmA, fmaxf(s[nb][0], s[nb][1]));
            tmB = fmaxf(tmB, fmaxf(s[nb][2], s[nb][3]));
        }
        tmA = fmaxf(tmA, __shfl_xor_sync(0xFFFFFFFFu, tmA, 1));
        tmA = fmaxf(tmA, __shfl_xor_sync(0xFFFFFFFFu, tmA, 2));
        tmB = fmaxf(tmB, __shfl_xor_sync(0xFFFFFFFFu, tmB, 1));
        tmB = fmaxf(tmB, __shfl_xor_sync(0xFFFFFFFFu, tmB, 2));

        const float mnA = fmaxf(mA, tmA);
        const float mnB = fmaxf(mB, tmB);
        const float cA = __expf(mA - mnA);
        const float cB = __expf(mB - mnB);
        lA *= cA;
        lB *= cB;
        #pragma unroll
        for (int nb = 0; nb < 8; nb++) {
            o[nb][0] *= cA; o[nb][1] *= cA;
            o[nb][2] *= cB; o[nb][3] *= cB;
        }

        #pragma unroll
        for (int nb = 0; nb < 8; nb++) {
            s[nb][0] = __expf(s[nb][0] - mnA);
            s[nb][1] = __expf(s[nb][1] - mnA);
            s[nb][2] = __expf(s[nb][2] - mnB);
            s[nb][3] = __expf(s[nb][3] - mnB);
            lA += s[nb][0] + s[nb][1];
            lB += s[nb][2] + s[nb][3];
        }

        const int src1 = gid * 4 + (tig >> 1);
        const int src2 = src1 + 2;
        const bool odd = (tig & 1);
        uint32_t pa[8][4];
        #pragma unroll
        for (int k8 = 0; k8 < 8; k8++) {
            float v0 = __shfl_sync(0xFFFFFFFFu, s[k8][0], src1);
            float v1 = __shfl_sync(0xFFFFFFFFu, s[k8][1], src1);
            float v2 = __shfl_sync(0xFFFFFFFFu, s[k8][2], src1);
            float v3 = __shfl_sync(0xFFFFFFFFu, s[k8][3], src1);
            float u0 = __shfl_sync(0xFFFFFFFFu, s[k8][0], src2);
            float u1 = __shfl_sync(0xFFFFFFFFu, s[k8][1], src2);
            float u2 = __shfl_sync(0xFFFFFFFFu, s[k8][2], src2);
            float u3 = __shfl_sync(0xFFFFFFFFu, s[k8][3], src2);
            pa[k8][0] = f2tf32(odd ? v1 : v0);
            pa[k8][1] = f2tf32(odd ? v3 : v2);
            pa[k8][2] = f2tf32(odd ? u1 : u0);
            pa[k8][3] = f2tf32(odd ? u3 : u2);
        }

        #pragma unroll
        for (int nb = 0; nb < 8; nb++) {
            #pragma unroll
            for (int k8 = 0; k8 < 8; k8++) {
                const float2 b = *(const float2*)&Vs[((nb * 8 + k8) * 32 + lane) << 1];
                mma_tf32(o[nb], pa[k8], (const uint32_t*)&b);
            }
        }

        mA = mnA;
        mB = mnB;
    }

    lA += __shfl_xor_sync(0xFFFFFFFFu, lA, 1);
    lA += __shfl_xor_sync(0xFFFFFFFFu, lA, 2);
    lB += __shfl_xor_sync(0xFFFFFFFFu, lB, 1);
    lB += __shfl_xor_sync(0xFFFFFFFFu, lB, 2);
    const float invA = 1.0f / lA;
    const float invB = 1.0f / lB;

    float* oa = o_out + (size_t)rowA * INNER + h * DHEAD;
    float* ob = o_out + (size_t)rowB * INNER + h * DHEAD;
    #pragma unroll
    for (int nb = 0; nb < 8; nb++) {
        const int c = nb * 8 + 2 * tig;
        float2 va; va.x = rnd_tf32(o[nb][0] * invA); va.y = rnd_tf32(o[nb][1] * invA);
        float2 vb; vb.x = rnd_tf32(o[nb][2] * invB); vb.y = rnd_tf32(o[nb][3] * invB);
        *(float2*)(oa + c) = va;
        *(float2*)(ob + c) = vb;
    }
}

// ---------------- orchestration ----------------
extern "C" void kernel_launch(void* const* d_in, const int* in_sizes, int n_in,
                              void* d_out, int out_size) {
    const float* x      = (const float*)d_in[0];
    const float* qkv_w  = (const float*)d_in[1];
    const float* out_w  = (const float*)d_in[2];
    const float* attn_g = (const float*)d_in[3];
    const float* attn_b = (const float*)d_in[4];
    const float* ff_g   = (const float*)d_in[5];
    const float* ff_b   = (const float*)d_in[6];
    const float* ff_w1  = (const float*)d_in[7];
    const float* ff_b1  = (const float*)d_in[8];
    const float* ff_w2  = (const float*)d_in[9];
    const float* ff_b2  = (const float*)d_in[10];
    const float* fin_g  = (const float*)d_in[11];
    const float* fin_b  = (const float*)d_in[12];
    float* out = (float*)d_out;

    float *h, *y, *qkv, *o, *z, *qkvT, *outT, *ff1T, *ff2T;
    cudaGetSymbolAddress((void**)&h,    g_h);
    cudaGetSymbolAddress((void**)&y,    g_y);
    cudaGetSymbolAddress((void**)&qkv,  g_qkv);
    cudaGetSymbolAddress((void**)&o,    g_o);
    cudaGetSymbolAddress((void**)&z,    g_z);
    cudaGetSymbolAddress((void**)&qkvT, g_qkvT);
    cudaGetSymbolAddress((void**)&outT, g_outT);
    cudaGetSymbolAddress((void**)&ff1T, g_ff1T);
    cudaGetSymbolAddress((void**)&ff2T, g_ff2T);

    // dynamic smem: 3 stages * (128 + BN) * 20 floats
    const int SMEM128 = GSTAGES * (128 + 128) * 20 * 4;  // 61440
    const int SMEM64  = GSTAGES * (128 + 64)  * 20 * 4;  // 46080
    static bool attr_done = false;
    if (!attr_done) {
        cudaFuncSetAttribute(mma_gemm<128>, cudaFuncAttributeMaxDynamicSharedMemorySize, SMEM128);
        cudaFuncSetAttribute(mma_gemm<64>,  cudaFuncAttributeMaxDynamicSharedMemorySize, SMEM64);
        attr_done = true;
    }

    // weight prep: [K][N] -> [N][K], tf32-rounded
    transpose_k<<<dim3(QKVW / 32, DIM / 32, LAYERS),  dim3(32, 8)>>>(qkv_w, qkvT, DIM, QKVW);
    transpose_k<<<dim3(DIM / 32, INNER / 32, LAYERS), dim3(32, 8)>>>(out_w, outT, INNER, DIM);
    transpose_k<<<dim3(FFDIM / 32, DIM / 32, LAYERS), dim3(32, 8)>>>(ff_w1, ff1T, DIM, FFDIM);
    transpose_k<<<dim3(DIM / 32, FFDIM / 32, LAYERS), dim3(32, 8)>>>(ff_w2, ff2T, FFDIM, DIM);

    cudaMemcpyAsync(h, x, (size_t)N_TOK * DIM * sizeof(float),
                    cudaMemcpyDeviceToDevice);

    for (int l = 0; l < LAYERS; l++) {
        // ---- attention block ----
        ln_kernel<true><<<N_TOK, 256>>>(h, attn_g + l * DIM, attn_b + l * DIM, y);
        mma_gemm<128><<<dim3(QKVW / 128, N_TOK / 128), 256, SMEM128>>>(
            y, qkvT + (size_t)l * QKVW * DIM, nullptr, nullptr, qkv,
            N_TOK, QKVW, DIM, FLAG_ROUND);
        attn_mma_kernel<<<dim3(N_TOK / 64, HEADS), 128>>>(qkv, o);
        mma_gemm<64><<<dim3(DIM / 64, N_TOK / 128), 128, SMEM64>>>(
            o, outT + (size_t)l * DIM * INNER, nullptr, h, h,
            N_TOK, DIM, INNER, FLAG_RES);
        // ---- feed-forward block ----
        ln_kernel<true><<<N_TOK, 256>>>(h, ff_g + l * DIM, ff_b + l * DIM, y);
        mma_gemm<128><<<dim3(FFDIM / 128, N_TOK / 128), 256, SMEM128>>>(
            y, ff1T + (size_t)l * FFDIM * DIM, ff_b1 + (size_t)l * FFDIM,
            nullptr, z, N_TOK, FFDIM, DIM, FLAG_BIAS | FLAG_GELU | FLAG_ROUND);
        mma_gemm<64><<<dim3(DIM / 64, N_TOK / 128), 128, SMEM64>>>(
            z, ff2T + (size_t)l * DIM * FFDIM, ff_b2 + (size_t)l * DIM,
            h, h, N_TOK, DIM, FFDIM, FLAG_BIAS | FLAG_RES);
    }
    ln_kernel<false><<<N_TOK, 256>>>(h, fin_g, fin_b, out);
}

// round 7
// speedup vs baseline: 7.5656x; 2.2288x over previous
#include <cuda_runtime.h>
#include <cuda_fp16.h>
#include <math.h>
#include <stdint.h>

#define N_TOK 2048
#define DIM   1024
#define HEADS 16
#define DHEAD 64
#define INNER 1024
#define FFDIM 4096
#define LAYERS 4
#define QKVW  (3*INNER)

// ---------------- scratch (no allocation allowed) ----------------
__device__ float  g_h  [N_TOK * DIM];
__device__ __half g_y  [N_TOK * DIM];
__device__ __half g_qkv[N_TOK * QKVW];
__device__ __half g_o  [N_TOK * INNER];
__device__ __half g_z  [N_TOK * FFDIM];
// transposed fp16 weights, [N][K] row-major
__device__ __half g_qkvT[LAYERS * QKVW * DIM];
__device__ __half g_outT[LAYERS * DIM * INNER];
__device__ __half g_ff1T[LAYERS * FFDIM * DIM];
__device__ __half g_ff2T[LAYERS * DIM * FFDIM];

__device__ __forceinline__ float gelu_exact(float x) {
    return 0.5f * x * (1.0f + erff(x * 0.70710678118654752f));
}
__device__ __forceinline__ uint32_t smem_u32(const void* p) {
    uint32_t a;
    asm("{ .reg .u64 t; cvta.to.shared.u64 t, %1; cvt.u32.u64 %0, t; }"
        : "=r"(a) : "l"(p));
    return a;
}
__device__ __forceinline__ void mma_f16(float* c, const uint32_t* a, const uint32_t* b) {
    asm volatile(
        "mma.sync.aligned.m16n8k16.row.col.f32.f16.f16.f32 "
        "{%0,%1,%2,%3}, {%4,%5,%6,%7}, {%8,%9}, {%0,%1,%2,%3};"
        : "+f"(c[0]), "+f"(c[1]), "+f"(c[2]), "+f"(c[3])
        : "r"(a[0]), "r"(a[1]), "r"(a[2]), "r"(a[3]),
          "r"(b[0]), "r"(b[1]));
}
#define LDSM_X4(r0, r1, r2, r3, addr) \
    asm volatile("ldmatrix.sync.aligned.m8n8.x4.shared.b16 {%0,%1,%2,%3}, [%4];" \
                 : "=r"(r0), "=r"(r1), "=r"(r2), "=r"(r3) : "r"(addr))
#define LDSM_X4_T(r0, r1, r2, r3, addr) \
    asm volatile("ldmatrix.sync.aligned.m8n8.x4.trans.shared.b16 {%0,%1,%2,%3}, [%4];" \
                 : "=r"(r0), "=r"(r1), "=r"(r2), "=r"(r3) : "r"(addr))
__device__ __forceinline__ void cp_async16(uint32_t dst, const void* src) {
    asm volatile("cp.async.ca.shared.global [%0], [%1], 16;" :: "r"(dst), "l"(src));
}
#define CP_COMMIT() asm volatile("cp.async.commit_group;" ::: "memory")
#define CP_WAIT(n)  asm volatile("cp.async.wait_group %0;" :: "n"(n) : "memory")
__device__ __forceinline__ uint32_t pack_h2(float a, float b) {
    __half2 h = __floats2half2_rn(a, b);
    return *(uint32_t*)&h;
}

// ---------------- layernorm: one block per row ----------------
template<bool HOUT>
__global__ void ln_kernel(const float* __restrict__ in,
                          const float* __restrict__ g,
                          const float* __restrict__ b,
                          void* __restrict__ outv) {
    int row = blockIdx.x;
    int tid = threadIdx.x;
    float4 v = ((const float4*)(in + (size_t)row * DIM))[tid];
    float s = v.x + v.y + v.z + v.w;
    float q = v.x*v.x + v.y*v.y + v.z*v.z + v.w*v.w;
    #pragma unroll
    for (int off = 16; off; off >>= 1) {
        s += __shfl_xor_sync(0xFFFFFFFFu, s, off);
        q += __shfl_xor_sync(0xFFFFFFFFu, q, off);
    }
    __shared__ float ss[8], qq[8];
    __shared__ float mean_s, rstd_s;
    int w = tid >> 5;
    if ((tid & 31) == 0) { ss[w] = s; qq[w] = q; }
    __syncthreads();
    if (tid == 0) {
        float S = 0.f, Q = 0.f;
        #pragma unroll
        for (int i = 0; i < 8; i++) { S += ss[i]; Q += qq[i]; }
        float mean = S * (1.0f / DIM);
        float var  = Q * (1.0f / DIM) - mean * mean;
        mean_s = mean;
        rstd_s = rsqrtf(var + 1e-5f);
    }
    __syncthreads();
    float mean = mean_s, rstd = rstd_s;
    float4 gg = ((const float4*)g)[tid];
    float4 bb = ((const float4*)b)[tid];
    float ox = (v.x - mean) * rstd * gg.x + bb.x;
    float oy = (v.y - mean) * rstd * gg.y + bb.y;
    float oz = (v.z - mean) * rstd * gg.z + bb.z;
    float ow = (v.w - mean) * rstd * gg.w + bb.w;
    if (HOUT) {
        uint2 o2;
        o2.x = pack_h2(ox, oy);
        o2.y = pack_h2(oz, ow);
        ((uint2*)((__half*)outv + (size_t)row * DIM))[tid] = o2;
    } else {
        float4 o;
        o.x = ox; o.y = oy; o.z = oz; o.w = ow;
        ((float4*)((float*)outv + (size_t)row * DIM))[tid] = o;
    }
}

// ---------------- weight transpose [L][K][N] -> [L][N][K], fp16 ----------
__global__ void transpose_k(const float* __restrict__ in, __half* __restrict__ out,
                            int K, int N) {
    __shared__ float t[32][33];
    int z = blockIdx.z;
    const float* ip = in + (size_t)z * K * N;
    __half* op = out + (size_t)z * K * N;
    int k0 = blockIdx.y * 32, n0 = blockIdx.x * 32;
    int tx = threadIdx.x, ty = threadIdx.y;  // 32 x 8
    #pragma unroll
    for (int j = 0; j < 32; j += 8)
        t[ty + j][tx] = ip[(size_t)(k0 + ty + j) * N + n0 + tx];
    __syncthreads();
    #pragma unroll
    for (int j = 0; j < 32; j += 8)
        op[(size_t)(n0 + ty + j) * K + k0 + tx] = __float2half_rn(t[tx][ty + j]);
}

// ---------------- FP16 GEMM: ldmatrix + cp.async 3-stage ------------------
// C[M,N] = A[M,K] @ BT[N,K]^T  (+bias)(gelu)(+res); A,BT fp16; acc fp32.
// BM=128, BN in {128,64}; warp tile 64x32; BK=32 halves (2x k16 per slab).
#define FLAG_BIAS  1
#define FLAG_GELU  2
#define FLAG_RES   4
#define GSTAGES 3

template<int BN, bool HOUT>
__global__ __launch_bounds__(BN * 2)
void mma_gemm(const __half* __restrict__ A, const __half* __restrict__ BT,
              const float* __restrict__ bias, const float* __restrict__ res,
              void* __restrict__ Cv, int M, int N, int K, int flags) {
    constexpr int THREADS = BN * 2;           // 256 or 128
    constexpr int BM = 128, BK = 32;          // halves per slab
    constexpr int RSTH = 40;                  // padded row stride (halves), 80B
    constexpr int SAH = BM * RSTH;            // halves
    constexpr int SBH = BN * RSTH;
    constexpr int STAGE_B = (SAH + SBH) * 2;  // bytes
    constexpr int WN = BN / 32;
    constexpr int AIT = (BM * 4) / THREADS;   // 16B chunks per thread (A)
    constexpr int BIT = (BN * 4) / THREADS;

    extern __shared__ __half smh[];
    const uint32_t sb0 = smem_u32(smh);

    const int tid  = threadIdx.x;
    const int lane = tid & 31;
    const int wid  = tid >> 5;
    const int gid  = lane >> 2;
    const int tig  = lane & 3;
    const int warp_m = wid / WN;
    const int warp_n = wid % WN;
    const int row0 = blockIdx.y * BM;
    const int col0 = blockIdx.x * BN;

    // lane parts of ldmatrix addresses (bytes)
    const uint32_t aLane = (warp_m * 64 + (lane & 15)) * 80 + (lane >> 4) * 16;
    const uint32_t bLane = SAH * 2
        + (warp_n * 32 + (lane & 7) + ((lane >> 4) & 1) * 8) * 80
        + ((lane >> 3) & 1) * 16;

    float acc[4][4][4];
    #pragma unroll
    for (int i = 0; i < 4; i++)
        #pragma unroll
        for (int j = 0; j < 4; j++)
            #pragma unroll
            for (int r = 0; r < 4; r++) acc[i][j][r] = 0.f;

    auto load_stage = [&](int s, int k0) {
        const uint32_t base = sb0 + s * STAGE_B;
        #pragma unroll
        for (int i = 0; i < AIT; i++) {
            const int f = tid + i * THREADS;
            const int r = f >> 2, c = f & 3;
            cp_async16(base + r * 80 + c * 16,
                       A + (size_t)(row0 + r) * K + k0 + c * 8);
        }
        #pragma unroll
        for (int i = 0; i < BIT; i++) {
            const int f = tid + i * THREADS;
            const int n = f >> 2, c = f & 3;
            cp_async16(base + SAH * 2 + n * 80 + c * 16,
                       BT + (size_t)(col0 + n) * K + k0 + c * 8);
        }
    };

    const int KT = K / BK;
    load_stage(0, 0);
    CP_COMMIT();
    load_stage(1, BK);
    CP_COMMIT();

    for (int kt = 0; kt < KT; kt++) {
        const int s = kt % GSTAGES;
        CP_WAIT(1);
        __syncthreads();

        if (kt + 2 < KT) load_stage((kt + 2) % GSTAGES, (kt + 2) * BK);
        CP_COMMIT();

        const uint32_t base = sb0 + s * STAGE_B;
        const uint32_t aW = base + aLane;
        const uint32_t bW = base + bLane;

        #pragma unroll
        for (int j = 0; j < 2; j++) {          // two k16 steps
            uint32_t af[4][4];
            #pragma unroll
            for (int fm = 0; fm < 4; fm++)
                LDSM_X4(af[fm][0], af[fm][1], af[fm][2], af[fm][3],
                        aW + fm * (16 * 80) + j * 32);
            uint32_t bf[2][4];                  // [fn2]{nlo b0, nlo b1, nhi b0, nhi b1}
            #pragma unroll
            for (int fn2 = 0; fn2 < 2; fn2++)
                LDSM_X4(bf[fn2][0], bf[fn2][1], bf[fn2][2], bf[fn2][3],
                        bW + fn2 * (16 * 80) + j * 32);
            #pragma unroll
            for (int fm = 0; fm < 4; fm++)
                #pragma unroll
                for (int fn = 0; fn < 4; fn++)
                    mma_f16(acc[fm][fn], af[fm], &bf[fn >> 1][(fn & 1) * 2]);
        }
    }

    // epilogue
    #pragma unroll
    for (int fm = 0; fm < 4; fm++) {
        const int r0 = row0 + warp_m * 64 + fm * 16 + gid;
        #pragma unroll
        for (int fn = 0; fn < 4; fn++) {
            const int c = col0 + warp_n * 32 + fn * 8 + tig * 2;
            #pragma unroll
            for (int half = 0; half < 2; half++) {
                const int r = r0 + half * 8;
                float vx = acc[fm][fn][half * 2 + 0];
                float vy = acc[fm][fn][half * 2 + 1];
                if (flags & FLAG_BIAS) {
                    vx += bias[c];
                    vy += bias[c + 1];
                }
                if (flags & FLAG_GELU) {
                    vx = gelu_exact(vx);
                    vy = gelu_exact(vy);
                }
                if (flags & FLAG_RES) {
                    const float2 rr = *(const float2*)&res[(size_t)r * N + c];
                    vx += rr.x;
                    vy += rr.y;
                }
                if (HOUT) {
                    uint32_t p = pack_h2(vx, vy);
                    *(uint32_t*)((__half*)Cv + (size_t)r * N + c) = p;
                } else {
                    float2 v; v.x = vx; v.y = vy;
                    *(float2*)((float*)Cv + (size_t)r * N + c) = v;
                }
            }
        }
    }
}

// ---------------- flash attention, fp16 mma m16n8k16 ----------------------
// grid (32, 16), block 128 (4 warps); warp owns 16 q rows. KV tile = 64 keys.
__global__ __launch_bounds__(128)
void attn_mma_kernel(const __half* __restrict__ qkv, __half* __restrict__ o_out) {
    const int h    = blockIdx.y;
    const int qt   = blockIdx.x;
    const int tid  = threadIdx.x;
    const int w    = tid >> 5;
    const int lane = tid & 31;
    const int gid  = lane >> 2;
    const int tig  = lane & 3;
    const float slope = exp2f(-0.5f * (float)(h + 1));

    __shared__ __half Kh[64 * 72];   // [key][d], stride 72 halves (144B)
    __shared__ __half Vh[64 * 72];
    const uint32_t kbase = smem_u32(Kh);
    const uint32_t vbase = smem_u32(Vh);

    const int rowA = qt * 64 + w * 16 + gid;
    const int rowB = rowA + 8;

    // Q fragments (x 0.125), 4 k16 blocks
    uint32_t qf[4][4];
    {
        const __half2 sc = __float2half2_rn(0.125f);
        const __half* qa = qkv + (size_t)rowA * QKVW + h * DHEAD;
        const __half* qb = qkv + (size_t)rowB * QKVW + h * DHEAD;
        #pragma unroll
        for (int j = 0; j < 4; j++) {
            __half2 v;
            v = __hmul2(*(const __half2*)(qa + 16*j + 2*tig),     sc); qf[j][0] = *(uint32_t*)&v;
            v = __hmul2(*(const __half2*)(qb + 16*j + 2*tig),     sc); qf[j][1] = *(uint32_t*)&v;
            v = __hmul2(*(const __half2*)(qa + 16*j + 8 + 2*tig), sc); qf[j][2] = *(uint32_t*)&v;
            v = __hmul2(*(const __half2*)(qb + 16*j + 8 + 2*tig), sc); qf[j][3] = *(uint32_t*)&v;
        }
    }

    float o[8][4];
    #pragma unroll
    for (int i = 0; i < 8; i++)
        #pragma unroll
        for (int r = 0; r < 4; r++) o[i][r] = 0.f;
    float mA = -INFINITY, mB = -INFINITY, lA = 0.f, lB = 0.f;

    for (int kt = 0; kt <= qt; kt++) {
        __syncthreads();
        // stage K/V tile: pure 16B copies (already fp16 in gmem)
        #pragma unroll
        for (int i = 0; i < 4; i++) {
            const int idx = tid + i * 128;
            const int key = idx >> 3, c = idx & 7;
            const __half* kp = qkv + (size_t)(kt * 64 + key) * QKVW + INNER + h * DHEAD + c * 8;
            *(uint4*)(Kh + key * 72 + c * 8) = *(const uint4*)kp;
            *(uint4*)(Vh + key * 72 + c * 8) = *(const uint4*)(kp + INNER);
        }
        __syncthreads();

        // ---- S = Q K^T : 8 n-blocks (keys) x 4 k16 (d) ----
        float s[8][4];
        #pragma unroll
        for (int nb2 = 0; nb2 < 4; nb2++) {
            #pragma unroll
            for (int r = 0; r < 4; r++) { s[2*nb2][r] = 0.f; s[2*nb2+1][r] = 0.f; }
            const uint32_t addr0 = kbase
                + (nb2 * 16 + (lane & 7) + ((lane >> 4) & 1) * 8) * 144
                + ((lane >> 3) & 1) * 16;
            #pragma unroll
            for (int j = 0; j < 4; j++) {
                uint32_t kb[4];
                LDSM_X4(kb[0], kb[1], kb[2], kb[3], addr0 + j * 32);
                mma_f16(s[2*nb2],     qf[j], &kb[0]);
                mma_f16(s[2*nb2 + 1], qf[j], &kb[2]);
            }
        }

        // ---- ALiBi + causal mask + row max ----
        const int cb = kt * 64;
        float tmA = -INFINITY, tmB = -INFINITY;
        #pragma unroll
        for (int nb = 0; nb < 8; nb++) {
            const int c0 = cb + nb * 8 + 2 * tig;
            s[nb][0] += slope * (float)c0;
            s[nb][1] += slope * (float)(c0 + 1);
            s[nb][2] += slope * (float)c0;
            s[nb][3] += slope * (float)(c0 + 1);
            if (kt == qt) {
                if (c0     > rowA) s[nb][0] = -INFINITY;
                if (c0 + 1 > rowA) s[nb][1] = -INFINITY;
                if (c0     > rowB) s[nb][2] = -INFINITY;
                if (c0 + 1 > rowB) s[nb][3] = -INFINITY;
            }
            tmA = fmaxf(tmA, fmaxf(s[nb][0], s[nb][1]));
            tmB = fmaxf(tmB, fmaxf(s[nb][2], s[nb][3]));
        }
        tmA = fmaxf(tmA, __shfl_xor_sync(0xFFFFFFFFu, tmA, 1));
        tmA = fmaxf(tmA, __shfl_xor_sync(0xFFFFFFFFu, tmA, 2));
        tmB = fmaxf(tmB, __shfl_xor_sync(0xFFFFFFFFu, tmB, 1));
        tmB = fmaxf(tmB, __shfl_xor_sync(0xFFFFFFFFu, tmB, 2));

        const float mnA = fmaxf(mA, tmA);
        const float mnB = fmaxf(mB, tmB);
        const float cA = __expf(mA - mnA);
        const float cB = __expf(mB - mnB);
        lA *= cA;
        lB *= cB;
        #pragma unroll
        for (int nb = 0; nb < 8; nb++) {
            o[nb][0] *= cA; o[nb][1] *= cA;
            o[nb][2] *= cB; o[nb][3] *= cB;
        }

        // ---- P = exp(S - m); pack directly into A-fragments (no shuffles) ----
        uint32_t pa[4][4];
        #pragma unroll
        for (int nb = 0; nb < 8; nb++) {
            s[nb][0] = __expf(s[nb][0] - mnA);
            s[nb][1] = __expf(s[nb][1] - mnA);
            s[nb][2] = __expf(s[nb][2] - mnB);
            s[nb][3] = __expf(s[nb][3] - mnB);
            lA += s[nb][0] + s[nb][1];
            lB += s[nb][2] + s[nb][3];
        }
        #pragma unroll
        for (int j = 0; j < 4; j++) {
            pa[j][0] = pack_h2(s[2*j][0],     s[2*j][1]);
            pa[j][1] = pack_h2(s[2*j][2],     s[2*j][3]);
            pa[j][2] = pack_h2(s[2*j+1][0],   s[2*j+1][1]);
            pa[j][3] = pack_h2(s[2*j+1][2],   s[2*j+1][3]);
        }

        // ---- O += P V : 8 n-blocks (d) x 4 k16 (keys); V^T via ldmatrix.trans
        #pragma unroll
        for (int dn2 = 0; dn2 < 4; dn2++) {
            #pragma unroll
            for (int j = 0; j < 4; j++) {
                uint32_t vb[4];
                LDSM_X4_T(vb[0], vb[1], vb[2], vb[3],
                    vbase + (16 * j + (lane & 7) + ((lane >> 3) & 1) * 8) * 144
                          + dn2 * 32 + ((lane >> 4) & 1) * 16);
                mma_f16(o[2*dn2],     pa[j], &vb[0]);
                mma_f16(o[2*dn2 + 1], pa[j], &vb[2]);
            }
        }

        mA = mnA;
        mB = mnB;
    }

    lA += __shfl_xor_sync(0xFFFFFFFFu, lA, 1);
    lA += __shfl_xor_sync(0xFFFFFFFFu, lA, 2);
    lB += __shfl_xor_sync(0xFFFFFFFFu, lB, 1);
    lB += __shfl_xor_sync(0xFFFFFFFFu, lB, 2);
    const float invA = 1.0f / lA;
    const float invB = 1.0f / lB;

    __half* oa = o_out + (size_t)rowA * INNER + h * DHEAD;
    __half* ob = o_out + (size_t)rowB * INNER + h * DHEAD;
    #pragma unroll
    for (int nb = 0; nb < 8; nb++) {
        const int c = nb * 8 + 2 * tig;
        *(uint32_t*)(oa + c) = pack_h2(o[nb][0] * invA, o[nb][1] * invA);
        *(uint32_t*)(ob + c) = pack_h2(o[nb][2] * invB, o[nb][3] * invB);
    }
}

// ---------------- orchestration ----------------
extern "C" void kernel_launch(void* const* d_in, const int* in_sizes, int n_in,
                              void* d_out, int out_size) {
    const float* x      = (const float*)d_in[0];
    const float* qkv_w  = (const float*)d_in[1];
    const float* out_w  = (const float*)d_in[2];
    const float* attn_g = (const float*)d_in[3];
    const float* attn_b = (const float*)d_in[4];
    const float* ff_g   = (const float*)d_in[5];
    const float* ff_b   = (const float*)d_in[6];
    const float* ff_w1  = (const float*)d_in[7];
    const float* ff_b1  = (const float*)d_in[8];
    const float* ff_w2  = (const float*)d_in[9];
    const float* ff_b2  = (const float*)d_in[10];
    const float* fin_g  = (const float*)d_in[11];
    const float* fin_b  = (const float*)d_in[12];
    float* out = (float*)d_out;

    float* h;
    __half *y, *qkv, *o, *z, *qkvT, *outT, *ff1T, *ff2T;
    cudaGetSymbolAddress((void**)&h,    g_h);
    cudaGetSymbolAddress((void**)&y,    g_y);
    cudaGetSymbolAddress((void**)&qkv,  g_qkv);
    cudaGetSymbolAddress((void**)&o,    g_o);
    cudaGetSymbolAddress((void**)&z,    g_z);
    cudaGetSymbolAddress((void**)&qkvT, g_qkvT);
    cudaGetSymbolAddress((void**)&outT, g_outT);
    cudaGetSymbolAddress((void**)&ff1T, g_ff1T);
    cudaGetSymbolAddress((void**)&ff2T, g_ff2T);

    // dynamic smem: 3 stages * (128 + BN) * 40 halves
    const int SMEM128 = GSTAGES * (128 + 128) * 40 * 2;  // 61440
    const int SMEM64  = GSTAGES * (128 + 64)  * 40 * 2;  // 46080
    static bool attr_done = false;
    if (!attr_done) {
        cudaFuncSetAttribute(mma_gemm<128, true>,
                             cudaFuncAttributeMaxDynamicSharedMemorySize, SMEM128);
        cudaFuncSetAttribute(mma_gemm<64, false>,
                             cudaFuncAttributeMaxDynamicSharedMemorySize, SMEM64);
        attr_done = true;
    }

    // weight prep: [K][N] fp32 -> [N][K] fp16
    transpose_k<<<dim3(QKVW / 32, DIM / 32, LAYERS),  dim3(32, 8)>>>(qkv_w, qkvT, DIM, QKVW);
    transpose_k<<<dim3(DIM / 32, INNER / 32, LAYERS), dim3(32, 8)>>>(out_w, outT, INNER, DIM);
    transpose_k<<<dim3(FFDIM / 32, DIM / 32, LAYERS), dim3(32, 8)>>>(ff_w1, ff1T, DIM, FFDIM);
    transpose_k<<<dim3(DIM / 32, FFDIM / 32, LAYERS), dim3(32, 8)>>>(ff_w2, ff2T, FFDIM, DIM);

    cudaMemcpyAsync(h, x, (size_t)N_TOK * DIM * sizeof(float),
                    cudaMemcpyDeviceToDevice);

    for (int l = 0; l < LAYERS; l++) {
        // ---- attention block ----
        ln_kernel<true><<<N_TOK, 256>>>(h, attn_g + l * DIM, attn_b + l * DIM, y);
        mma_gemm<128, true><<<dim3(QKVW / 128, N_TOK / 128), 256, SMEM128>>>(
            y, qkvT + (size_t)l * QKVW * DIM, nullptr, nullptr, qkv,
            N_TOK, QKVW, DIM, 0);
        attn_mma_kernel<<<dim3(N_TOK / 64, HEADS), 128>>>(qkv, o);
        mma_gemm<64, false><<<dim3(DIM / 64, N_TOK / 128), 128, SMEM64>>>(
            o, outT + (size_t)l * DIM * INNER, nullptr, h, h,
            N_TOK, DIM, INNER, FLAG_RES);
        // ---- feed-forward block ----
        ln_kernel<true><<<N_TOK, 256>>>(h, ff_g + l * DIM, ff_b + l * DIM, y);
        mma_gemm<128, true><<<dim3(FFDIM / 128, N_TOK / 128), 256, SMEM128>>>(
            y, ff1T + (size_t)l * FFDIM * DIM, ff_b1 + (size_t)l * FFDIM,
            nullptr, z, N_TOK, FFDIM, DIM, FLAG_BIAS | FLAG_GELU);
        mma_gemm<64, false><<<dim3(DIM / 64, N_TOK / 128), 128, SMEM64>>>(
            z, ff2T + (size_t)l * DIM * FFDIM, ff_b2 + (size_t)l * DIM,
            h, h, N_TOK, DIM, FFDIM, FLAG_BIAS | FLAG_RES);
    }
    ln_kernel<false><<<N_TOK, 256>>>(h, fin_g, fin_b, out);
}